// round 10
// baseline (speedup 1.0000x reference)
#include <cuda_runtime.h>
#include <math.h>

#define CDIV(a,b) (((a)+(b)-1)/(b))
#define N_ANCH 76725
#define N_SORT 131072
#define KTOP   1000
#define TS     (256*8525)
typedef unsigned long long ull;

// dynamic smem: wBuf[2][9216] floats (8ci*9k*128co), inBuf[2 tiles][2 stages][1120] ull
#define WBUF_FLOATS 9216
#define INBUF_ULLS  1120
#define DYN_SMEM (2*WBUF_FLOATS*4 + 4*INBUF_ULLS*8)   // 73728 + 35840 = 109568 B

// ---------------- scratch (static device globals; no allocation) -------------
__device__ float g_bufA[2*TS];
__device__ float g_bufB[2*TS];
__device__ float g_wTrunk[2*4*256*9*256];      // [tower][layer][ci][k][co]
__device__ float g_wCls[256*9*768];
__device__ float g_wReg[256*9*128];
__device__ float g_cls[720*8525];
__device__ float g_reg[36*8525];
__device__ float g_scores[N_ANCH];
__device__ int   g_arg[N_ANCH];
__device__ float4 g_loc[N_ANCH];
__device__ ull   g_keys[N_SORT];
__device__ ull   g_tmpA[32*1024];
__device__ ull   g_tmpB[16*1024];
__device__ unsigned g_mask[KTOP*32];
__device__ float4 g_selBox[KTOP];
__device__ float  g_topVal[KTOP];
__device__ int    g_selCls[KTOP];
__device__ unsigned char g_keep[KTOP];

// ---------------- fused weight transpose -------------------------------------
#define TRKN (4*256*9*256)
__global__ void transpose_all_k(const float* __restrict__ cls_w,
                                const float* __restrict__ reg_w,
                                const float* __restrict__ cls_hw,
                                const float* __restrict__ reg_hw,
                                float* __restrict__ wTrk,
                                float* __restrict__ wCls,
                                float* __restrict__ wReg)
{
    int idx = blockIdx.x * blockDim.x + threadIdx.x;
    if (idx < 2*TRKN) {
        const float* src = (idx < TRKN) ? cls_w : reg_w;
        int i = (idx < TRKN) ? idx : idx - TRKN;
        int co = i & 255, r = i >> 8;
        int kk = r % 9, r2 = r / 9;
        int ci = r2 & 255, layer = r2 >> 8;
        wTrk[idx] = src[((layer*256 + co)*256 + ci)*9 + kk];
        return;
    }
    idx -= 2*TRKN;
    if (idx < 256*9*768) {
        int co = idx % 768, r = idx / 768;
        int kk = r % 9, ci = r / 9;
        wCls[idx] = (co < 720) ? cls_hw[(co*256 + ci)*9 + kk] : 0.f;
        return;
    }
    idx -= 256*9*768;
    if (idx < 256*9*128) {
        int co = idx % 128, r = idx / 128;
        int kk = r % 9, ci = r / 9;
        wReg[idx] = (co < 36) ? reg_hw[(co*256 + ci)*9 + kk] : 0.f;
    }
}

// ---------------- helpers ----------------------------------------------------
__device__ __forceinline__ void ffma2(ull& d, ull a, ull b) {
    asm("fma.rn.f32x2 %0, %1, %2, %0;" : "+l"(d) : "l"(a), "l"(b));
}
__device__ __forceinline__ ull pack2(float v) {
    ull r; asm("mov.b64 %0, {%1, %1};" : "=l"(r) : "f"(v)); return r;
}
__device__ __forceinline__ float lo32(ull a) { return __uint_as_float((unsigned)a); }
__device__ __forceinline__ float hi32(ull a) { return __uint_as_float((unsigned)(a >> 32)); }
__device__ __forceinline__ void cp_async16(unsigned saddr, const void* gptr) {
    asm volatile("cp.async.cg.shared.global [%0], [%1], 16;" :: "r"(saddr), "l"(gptr));
}
#define CP_COMMIT() asm volatile("cp.async.commit_group;")
#define CP_WAIT0()  asm volatile("cp.async.wait_group 0;")

__device__ __forceinline__ void tile_decode(int t, int& L, int& H, int& hwBase,
                                            int& x0, int& y0)
{
    int tpr;
    if      (t < 100) { L=0; H=80; hwBase=0;    tpr=10; }
    else if (t < 125) { L=1; H=40; hwBase=6400; tpr=5;  t-=100; }
    else if (t < 134) { L=2; H=20; hwBase=8000; tpr=3;  t-=125; }
    else if (t < 138) { L=3; H=10; hwBase=8400; tpr=2;  t-=134; }
    else              { L=4; H=5;  hwBase=8500; tpr=1;  t-=138; }
    x0 = (t % tpr) * 8; y0 = (t / tpr) * 8;
}

// ---------------- paired-tile conv core --------------------------------------
// Two pixel tiles share one weight stream. 32 chunks of 8 cin, weights and
// per-tile inputs double-buffered. Accumulation order identical to prior rounds.
struct TileGeom {
    const float* in;
    float* out;
    int H, HW, x0, y0;
    int gInv[4];
    bool okL[4];
};

__device__ __forceinline__ void conv_core_pair(
    const TileGeom& TA, const TileGeom& TB, bool hasB,
    const float* __restrict__ wT, int STR, int coBase,
    const float* __restrict__ bias, int Cout, int relu)
{
    extern __shared__ __align__(16) char dynsmem[];
    float* wBuf = (float*)dynsmem;                              // [2][9216]
    ull*   inBuf = (ull*)(dynsmem + 2*WBUF_FLOATS*4);           // [tile][stage][1120]

    const int tid = threadIdx.x;
    const int p = tid & 15, q = tid >> 4;
    const int pyb = (p >> 2) * 2, pxb = (p & 3) * 2;
    const int coQ = q * 8;

    // shared fill geometry (depends only on tid)
    int sAddr[4]; bool okS[4];
    #pragma unroll
    for (int j = 0; j < 4; j++) {
        int idx = tid + j * 256;
        int ci = idx / 100, r = idx % 100, dy = r / 10, dx = r % 10;
        okS[j] = idx < 800;
        sAddr[j] = ci * 140 + dy * 14 + dx;
    }

    // weight fill: 2304 16B chunks, 9 per thread
    auto issueW = [&](int chunk, int bIdx) {
        const float* wp = wT + chunk * 72 * STR + coBase;
        unsigned sb = (unsigned)__cvta_generic_to_shared(wBuf + bIdx * WBUF_FLOATS);
        #pragma unroll
        for (int c = 0; c < 9; c++) {
            int i = tid + c * 256;
            int row = i >> 5, lane = i & 31;
            cp_async16(sb + row * 512 + lane * 16, wp + row * STR + lane * 4);
        }
        CP_COMMIT();
    };
    auto loadIn = [&](const TileGeom& T, int chunk, float vreg[4]) {
        #pragma unroll
        for (int j = 0; j < 4; j++)
            vreg[j] = T.okL[j] ? __ldg(T.in + T.gInv[j] + chunk * 8 * T.HW) : 0.f;
    };
    auto storeIn = [&](int tile, int bIdx, const float vreg[4]) {
        #pragma unroll
        for (int j = 0; j < 4; j++)
            if (okS[j]) inBuf[(tile * 2 + bIdx) * INBUF_ULLS + sAddr[j]] = pack2(vreg[j]);
    };

    // prologue
    {
        float vA[4], vB[4];
        issueW(0, 0);
        loadIn(TA, 0, vA);
        if (hasB) loadIn(TB, 0, vB);
        storeIn(0, 0, vA);
        if (hasB) storeIn(1, 0, vB);
        CP_WAIT0();
    }
    __syncthreads();

    ull accA[2][2][4] = {};
    ull accB[2][2][4] = {};

    #pragma unroll 1
    for (int chunk = 0; chunk < 32; chunk++) {
        const int cur = chunk & 1;
        const bool more = (chunk + 1) < 32;
        float vA[4], vB[4];
        if (more) {
            issueW(chunk + 1, cur ^ 1);
            loadIn(TA, chunk + 1, vA);
            if (hasB) loadIn(TB, chunk + 1, vB);
        }

        const float* s_w = wBuf + cur * WBUF_FLOATS;

        #pragma unroll 1
        for (int tile = 0; tile < 2; tile++) {
            if (tile == 1 && !hasB) break;
            ull (*acc)[2][4] = (tile == 0) ? accA : accB;
            const ull* s_base = inBuf + (tile * 2 + cur) * INBUF_ULLS;

            #pragma unroll 1
            for (int ci = 0; ci < 8; ci++) {
                const ull* rowb = s_base + ci * 140;
                const float* wcb = s_w + ci * 9 * 128 + coQ;
                #pragma unroll
                for (int ky = 0; ky < 3; ky++) {
                    ull iv[2][4];
                    #pragma unroll
                    for (int r = 0; r < 2; r++) {
                        const ulonglong2* rp = (const ulonglong2*)(rowb + (pyb + ky + r) * 14 + pxb);
                        ulonglong2 v0 = rp[0], v1 = rp[1];
                        iv[r][0] = v0.x; iv[r][1] = v0.y; iv[r][2] = v1.x; iv[r][3] = v1.y;
                    }
                    #pragma unroll
                    for (int kx = 0; kx < 3; kx++) {
                        const float* wrow = wcb + (ky * 3 + kx) * 128;
                        ulonglong2 wa = *(const ulonglong2*)(wrow);
                        ulonglong2 wb = *(const ulonglong2*)(wrow + 4);
                        #pragma unroll
                        for (int py = 0; py < 2; py++)
                            #pragma unroll
                            for (int px = 0; px < 2; px++) {
                                ull v = iv[py][px + kx];
                                ffma2(acc[py][px][0], v, wa.x);
                                ffma2(acc[py][px][1], v, wa.y);
                                ffma2(acc[py][px][2], v, wb.x);
                                ffma2(acc[py][px][3], v, wb.y);
                            }
                    }
                }
            }
        }

        if (more) {
            storeIn(0, cur ^ 1, vA);
            if (hasB) storeIn(1, cur ^ 1, vB);
            CP_WAIT0();
        }
        __syncthreads();
    }

    // epilogue per tile
    #pragma unroll 1
    for (int tile = 0; tile < 2; tile++) {
        if (tile == 1 && !hasB) break;
        const TileGeom& T = (tile == 0) ? TA : TB;
        ull (*acc)[2][4] = (tile == 0) ? accA : accB;
        #pragma unroll
        for (int pr = 0; pr < 4; pr++) {
            int c0 = coBase + coQ + pr * 2, c1 = c0 + 1;
            if (c0 >= Cout) continue;
            float b0 = bias[c0];
            float b1 = (c1 < Cout) ? bias[c1] : 0.f;
            #pragma unroll
            for (int py = 0; py < 2; py++) {
                int y = T.y0 + pyb + py;
                if (y >= T.H) continue;
                #pragma unroll
                for (int px = 0; px < 2; px++) {
                    int x = T.x0 + pxb + px;
                    if (x >= T.H) continue;
                    float v0 = lo32(acc[py][px][pr]) + b0;
                    float v1 = hi32(acc[py][px][pr]) + b1;
                    if (relu) { v0 = fmaxf(v0, 0.f); v1 = fmaxf(v1, 0.f); }
                    T.out[c0 * T.HW + y * T.H + x] = v0;
                    if (c1 < Cout) T.out[c1 * T.HW + y * T.H + x] = v1;
                }
            }
        }
    }
}

__device__ __forceinline__ void make_geom(TileGeom& T, int t,
    const float* f0, const float* f1, const float* f2, const float* f3,
    const float* f4, const float* actIn, float* actOut, int tower, int isFirst,
    int outChans, float* outOverride)
{
    int L, H, hwBase, x0, y0;
    tile_decode(t, L, H, hwBase, x0, y0);
    T.H = H; T.HW = H * H; T.x0 = x0; T.y0 = y0;
    if (isFirst) {
        const float* fs[5] = {f0, f1, f2, f3, f4};
        T.in = fs[L];
    } else {
        T.in = actIn + tower * TS + hwBase * 256;
    }
    T.out = outOverride ? (outOverride + outChans * hwBase)
                        : (actOut + tower * TS + hwBase * 256);
    const int tid = threadIdx.x;
    #pragma unroll
    for (int j = 0; j < 4; j++) {
        int idx = tid + j * 256;
        int ci = idx / 100, r = idx % 100, dy = r / 10, dx = r % 10;
        int gy = y0 - 1 + dy, gx = x0 - 1 + dx;
        bool ok = (idx < 800) && gy >= 0 && gy < H && gx >= 0 && gx < H;
        T.okL[j] = ok;
        T.gInv[j] = ok ? (ci * T.HW + gy * H + gx) : 0;
    }
}

__global__ __launch_bounds__(256, 2)
void conv_trunk_k(const float* f0, const float* f1, const float* f2,
                  const float* f3, const float* f4,
                  const float* __restrict__ actIn, float* __restrict__ actOut,
                  const float* __restrict__ wT,
                  const float* __restrict__ biasCls, const float* __restrict__ biasReg,
                  int layer, int isFirst)
{
    const int t0 = blockIdx.x * 2, t1 = t0 + 1;
    const bool hasB = (t1 < 139);
    const int tower = blockIdx.z;
    const int coBase = blockIdx.y * 128;

    TileGeom TA, TB;
    make_geom(TA, t0, f0,f1,f2,f3,f4, actIn, actOut, tower, isFirst, 0, nullptr);
    make_geom(TB, hasB ? t1 : t0, f0,f1,f2,f3,f4, actIn, actOut, tower, isFirst, 0, nullptr);

    const float* w = wT + (tower * 4 + layer) * (256*9*256);
    const float* b = (tower ? biasReg : biasCls) + layer * 256;
    conv_core_pair(TA, TB, hasB, w, 256, coBase, b, 256, 1);
}

__global__ __launch_bounds__(256, 2)
void conv_head_k(const float* __restrict__ actIn,
                 float* __restrict__ outCls, float* __restrict__ outReg,
                 const float* __restrict__ wTc, const float* __restrict__ wTr,
                 const float* __restrict__ biasC, const float* __restrict__ biasR)
{
    const int t0 = blockIdx.x * 2, t1 = t0 + 1;
    const bool hasB = (t1 < 139);
    const int yy = blockIdx.y;
    TileGeom TA, TB;
    if (yy < 6) {
        make_geom(TA, t0, 0,0,0,0,0, actIn, nullptr, 0, 0, 720, outCls);
        make_geom(TB, hasB ? t1 : t0, 0,0,0,0,0, actIn, nullptr, 0, 0, 720, outCls);
        conv_core_pair(TA, TB, hasB, wTc, 768, yy * 128, biasC, 720, 0);
    } else {
        make_geom(TA, t0, 0,0,0,0,0, actIn, nullptr, 1, 0, 36, outReg);
        make_geom(TB, hasB ? t1 : t0, 0,0,0,0,0, actIn, nullptr, 1, 0, 36, outReg);
        conv_core_pair(TA, TB, hasB, wTr, 128, 0, biasR, 36, 0);
    }
}

// ---------------- fused scores/argmax/keys + block-local sort ----------------
__global__ __launch_bounds__(1024)
void score_key_sort_k(const float* __restrict__ cls_raw,
                      const float* __restrict__ reg_raw,
                      float* __restrict__ scores, int* __restrict__ arg,
                      float4* __restrict__ loc,
                      ull* __restrict__ keys)
{
    __shared__ ull s[2048];
    int tid = threadIdx.x;

    #pragma unroll
    for (int h = 0; h < 2; h++) {
        int t = blockIdx.x * 2048 + tid + h * 1024;
        ull key = 0xFFFFFFFFFFFFFFFFULL;
        if (t < N_ANCH) {
            int L, a, p, HW, cum;
            if      (t < 57600) { L=0; int rel=t;       HW=6400; a=rel/6400; p=rel%6400; cum=0;    }
            else if (t < 72000) { L=1; int rel=t-57600; HW=1600; a=rel/1600; p=rel%1600; cum=6400; }
            else if (t < 75600) { L=2; int rel=t-72000; HW=400;  a=rel/400;  p=rel%400;  cum=8000; }
            else if (t < 76500) { L=3; int rel=t-75600; HW=100;  a=rel/100;  p=rel%100;  cum=8400; }
            else                { L=4; int rel=t-76500; HW=25;   a=rel/25;   p=rel%25;   cum=8500; }
            const int aoff[5] = {0, 57600, 72000, 75600, 76500};
            int idx = aoff[L] + p * 9 + a;

            const float* cb = cls_raw + 720 * cum + (a * 80) * HW + p;
            float best = 1.f / (1.f + expf(-cb[0]));
            int barg = 0;
            for (int c = 1; c < 80; c++) {
                float sg = 1.f / (1.f + expf(-cb[c * HW]));
                if (sg > best) { best = sg; barg = c; }
            }
            float masked = (best > 0.05f) ? best : -1.0f;
            scores[idx] = masked;
            arg[idx] = barg;

            const float* rb = reg_raw + 36 * cum + (a * 4) * HW + p;
            loc[idx] = make_float4(rb[0], rb[HW], rb[2 * HW], rb[3 * HW]);

            unsigned u = __float_as_uint(masked);
            u = (u & 0x80000000u) ? ~u : (u | 0x80000000u);
            key = (((ull)(~u)) << 32) | (unsigned)idx;
        }
        s[tid + h * 1024] = key;
    }
    __syncthreads();

    for (int k = 2; k <= 2048; k <<= 1) {
        for (int j = k >> 1; j >= 1; j >>= 1) {
            #pragma unroll
            for (int h = 0; h < 2; h++) {
                int l = tid + h * 1024;
                int ixj = l ^ j;
                if (ixj > l) {
                    ull a = s[l], b = s[ixj];
                    bool up = ((l & k) == 0);
                    if ((a > b) == up) { s[l] = b; s[ixj] = a; }
                }
            }
            __syncthreads();
        }
    }
    keys[blockIdx.x * 2048 + tid] = s[tid];
    keys[blockIdx.x * 2048 + tid + 1024] = s[tid + 1024];
}

// ---------------- tournament merge -------------------------------------------
__global__ __launch_bounds__(512)
void topk_merge_k(const ull* __restrict__ in, ull* __restrict__ out, int inStride)
{
    __shared__ ull s[2048];
    int t = threadIdx.x;
    const ull* A = in + (size_t)blockIdx.x * 2 * inStride;
    const ull* B = A + inStride;
    #pragma unroll
    for (int i = t; i < 1024; i += 512) {
        s[i] = A[i];
        s[2047 - i] = B[i];
    }
    __syncthreads();
    for (int j = 1024; j >= 1; j >>= 1) {
        #pragma unroll
        for (int h = 0; h < 4; h++) {
            int l = t + h * 512;
            int ixj = l ^ j;
            if (ixj > l) {
                ull a = s[l], b = s[ixj];
                if (a > b) { s[l] = b; s[ixj] = a; }
            }
        }
        __syncthreads();
    }
    #pragma unroll
    for (int i = t; i < 1024; i += 512)
        out[blockIdx.x * 1024 + i] = s[i];
}

// ---------------- decode top-1000 boxes --------------------------------------
__device__ __forceinline__ void anchor_split(int idx, int& L, int& p, int& a, int& Wd)
{
    const int aoff[6] = {0, 57600, 72000, 75600, 76500, 76725};
    const int Ws[5] = {80, 40, 20, 10, 5};
    L = 0;
    while (L < 4 && idx >= aoff[L + 1]) L++;
    int rel = idx - aoff[L];
    p = rel / 9; a = rel - p * 9; Wd = Ws[L];
}

__global__ void decode_k(const ull* __restrict__ keys,
                         const float* __restrict__ scores,
                         const int* __restrict__ arg,
                         const float4* __restrict__ loc,
                         float4* __restrict__ selBox, float* __restrict__ topVal,
                         int* __restrict__ selCls)
{
    int r = blockIdx.x * blockDim.x + threadIdx.x;
    if (r >= KTOP) return;
    int idx = (int)(keys[r] & 0xFFFFFFFFULL);
    float val = scores[idx];
    topVal[r] = val;
    selCls[r] = arg[idx];

    const int strides[5] = {8, 16, 32, 64, 128};
    const int sizes[5] = {32, 64, 128, 256, 512};
    int L, p, a, W;
    anchor_split(idx, L, p, a, W);
    int y = p / W, x = p - y * W;
    int ri = a / 3, si = a - ri * 3;
    const float ratios[3] = {0.5f, 1.0f, 2.0f};
    const float scales[3] = {1.0f, 1.2599210498948732f, 1.5874010519681994f};
    float sq = sqrtf(ratios[ri]);
    float ws = (float)sizes[L] * scales[si] / sq;
    float hs = (float)sizes[L] * scales[si] * sq;
    float st = (float)strides[L];
    float cx = ((float)x + 0.5f) * st;
    float cy = ((float)y + 0.5f) * st;

    float4 l = loc[idx];
    float dx = l.x * 0.1f, dy = l.y * 0.1f, dw = l.z * 0.2f, dh = l.w * 0.2f;
    float pcx = cx + dx * ws, pcy = cy + dy * hs;
    float pw = expf(dw) * ws, ph = expf(dh) * hs;
    float bx1 = fminf(fmaxf(pcx - 0.5f * pw, 0.f), 640.f);
    float by1 = fminf(fmaxf(pcy - 0.5f * ph, 0.f), 640.f);
    float bx2 = fminf(fmaxf(pcx + 0.5f * pw, 0.f), 640.f);
    float by2 = fminf(fmaxf(pcy + 0.5f * ph, 0.f), 640.f);
    selBox[r] = make_float4(bx1, by1, bx2, by2);
}

// ---------------- NMS --------------------------------------------------------
__global__ __launch_bounds__(1024)
void iou_mask_k(const float4* __restrict__ boxes, unsigned* __restrict__ mask)
{
    int i = blockIdx.x;
    int j = threadIdx.x;
    float4 bi = boxes[i];
    float4 bj = (j < KTOP) ? boxes[j] : make_float4(0,0,0,0);
    float ai = fmaxf(bi.z - bi.x, 0.f) * fmaxf(bi.w - bi.y, 0.f);
    float aj = fmaxf(bj.z - bj.x, 0.f) * fmaxf(bj.w - bj.y, 0.f);
    float xx1 = fmaxf(bi.x, bj.x), yy1 = fmaxf(bi.y, bj.y);
    float xx2 = fminf(bi.z, bj.z), yy2 = fminf(bi.w, bj.w);
    float inter = fmaxf(xx2 - xx1, 0.f) * fmaxf(yy2 - yy1, 0.f);
    float iou = inter / (ai + aj - inter + 1e-8f);
    bool sup = (j < KTOP) && (j > i) && (iou > 0.5f);
    unsigned bal = __ballot_sync(0xffffffffu, sup);
    if ((j & 31) == 0) mask[i * 32 + (j >> 5)] = bal;
}

__global__ void nms_seq_k(const unsigned* __restrict__ mask,
                          const float* __restrict__ vals,
                          unsigned char* __restrict__ keepOut)
{
    int lane = threadIdx.x;
    unsigned validw = 0;
    #pragma unroll
    for (int b = 0; b < 32; b++) {
        int j = lane * 32 + b;
        if (j < KTOP && vals[j] > 0.f) validw |= (1u << b);
    }
    unsigned remv = 0;
    for (int i = 0; i < KTOP; i++) {
        unsigned row = mask[i * 32 + lane];
        unsigned rm = __shfl_sync(0xffffffffu, remv, i >> 5);
        unsigned vw = __shfl_sync(0xffffffffu, validw, i >> 5);
        unsigned bi = i & 31;
        if (((vw >> bi) & 1) && !((rm >> bi) & 1))
            remv |= row;
    }
    #pragma unroll
    for (int b = 0; b < 32; b++) {
        int j = lane * 32 + b;
        if (j < KTOP)
            keepOut[j] = (unsigned char)(((validw >> b) & 1) && !((remv >> b) & 1));
    }
}

// ---------------- pack output ------------------------------------------------
__global__ void output_k(const float* __restrict__ vals, const int* __restrict__ cls,
                         const float4* __restrict__ boxes,
                         const unsigned char* __restrict__ keep,
                         float* __restrict__ out, int out_size)
{
    int r = blockIdx.x * blockDim.x + threadIdx.x;
    if (r >= KTOP) return;
    bool k = keep[r] != 0;
    float4 b = boxes[r];
    if (r < out_size) out[r] = k ? vals[r] : 0.f;
    if (1000 + r < out_size) out[1000 + r] = (float)cls[r];
    if (2000 + 4 * r + 3 < out_size) {
        out[2000 + 4 * r + 0] = k ? b.x : 0.f;
        out[2000 + 4 * r + 1] = k ? b.y : 0.f;
        out[2000 + 4 * r + 2] = k ? b.z : 0.f;
        out[2000 + 4 * r + 3] = k ? b.w : 0.f;
    }
    if (6000 + r < out_size) out[6000 + r] = k ? 1.f : 0.f;
}

// ---------------- host orchestration -----------------------------------------
extern "C" void kernel_launch(void* const* d_in, const int* in_sizes, int n_in,
                              void* d_out, int out_size)
{
    (void)in_sizes; (void)n_in;
    const float* f0 = (const float*)d_in[0];
    const float* f1 = (const float*)d_in[1];
    const float* f2 = (const float*)d_in[2];
    const float* f3 = (const float*)d_in[3];
    const float* f4 = (const float*)d_in[4];
    const float* cls_w  = (const float*)d_in[5];
    const float* cls_b  = (const float*)d_in[6];
    const float* cls_hw = (const float*)d_in[7];
    const float* cls_hb = (const float*)d_in[8];
    const float* reg_w  = (const float*)d_in[9];
    const float* reg_b  = (const float*)d_in[10];
    const float* reg_hw = (const float*)d_in[11];
    const float* reg_hb = (const float*)d_in[12];

    float *bufA, *bufB, *wTrk, *wCls, *wReg, *clsR, *regR, *scores, *topVal;
    int *arg, *selCls;
    float4 *loc, *selBox;
    ull *keys, *tmpA, *tmpB;
    unsigned *mask;
    unsigned char* keep;
    cudaGetSymbolAddress((void**)&bufA, g_bufA);
    cudaGetSymbolAddress((void**)&bufB, g_bufB);
    cudaGetSymbolAddress((void**)&wTrk, g_wTrunk);
    cudaGetSymbolAddress((void**)&wCls, g_wCls);
    cudaGetSymbolAddress((void**)&wReg, g_wReg);
    cudaGetSymbolAddress((void**)&clsR, g_cls);
    cudaGetSymbolAddress((void**)&regR, g_reg);
    cudaGetSymbolAddress((void**)&scores, g_scores);
    cudaGetSymbolAddress((void**)&arg, g_arg);
    cudaGetSymbolAddress((void**)&loc, g_loc);
    cudaGetSymbolAddress((void**)&keys, g_keys);
    cudaGetSymbolAddress((void**)&tmpA, g_tmpA);
    cudaGetSymbolAddress((void**)&tmpB, g_tmpB);
    cudaGetSymbolAddress((void**)&mask, g_mask);
    cudaGetSymbolAddress((void**)&selBox, g_selBox);
    cudaGetSymbolAddress((void**)&topVal, g_topVal);
    cudaGetSymbolAddress((void**)&selCls, g_selCls);
    cudaGetSymbolAddress((void**)&keep, g_keep);

    static int smemSet = 0;
    if (!smemSet) {
        cudaFuncSetAttribute(conv_trunk_k, cudaFuncAttributeMaxDynamicSharedMemorySize, DYN_SMEM);
        cudaFuncSetAttribute(conv_head_k,  cudaFuncAttributeMaxDynamicSharedMemorySize, DYN_SMEM);
        smemSet = 1;
    }

    const int TOTW = 2*TRKN + 256*9*768 + 256*9*128;
    transpose_all_k<<<CDIV(TOTW,256), 256>>>(cls_w, reg_w, cls_hw, reg_hw, wTrk, wCls, wReg);

    dim3 gt(70, 2, 2);   // 280 blocks = one wave at 2 CTAs/SM
    conv_trunk_k<<<gt, 256, DYN_SMEM>>>(f0,f1,f2,f3,f4, nullptr, bufA, wTrk, cls_b, reg_b, 0, 1);
    conv_trunk_k<<<gt, 256, DYN_SMEM>>>(f0,f1,f2,f3,f4, bufA,    bufB, wTrk, cls_b, reg_b, 1, 0);
    conv_trunk_k<<<gt, 256, DYN_SMEM>>>(f0,f1,f2,f3,f4, bufB,    bufA, wTrk, cls_b, reg_b, 2, 0);
    conv_trunk_k<<<gt, 256, DYN_SMEM>>>(f0,f1,f2,f3,f4, bufA,    bufB, wTrk, cls_b, reg_b, 3, 0);
    dim3 gh(70, 7, 1);   // 490 blocks
    conv_head_k<<<gh, 256, DYN_SMEM>>>(bufB, clsR, regR, wCls, wReg, cls_hb, reg_hb);

    score_key_sort_k<<<N_SORT / 2048, 1024>>>(clsR, regR, scores, arg, loc, keys);

    topk_merge_k<<<32, 512>>>(keys, tmpA, 2048);
    topk_merge_k<<<16, 512>>>(tmpA, tmpB, 1024);
    topk_merge_k<<< 8, 512>>>(tmpB, tmpA, 1024);
    topk_merge_k<<< 4, 512>>>(tmpA, tmpB, 1024);
    topk_merge_k<<< 2, 512>>>(tmpB, tmpA, 1024);
    topk_merge_k<<< 1, 512>>>(tmpA, tmpB, 1024);

    decode_k<<<CDIV(KTOP, 256), 256>>>(tmpB, scores, arg, loc, selBox, topVal, selCls);
    iou_mask_k<<<KTOP, 1024>>>(selBox, mask);
    nms_seq_k<<<1, 32>>>(mask, topVal, keep);
    output_k<<<CDIV(KTOP, 256), 256>>>(topVal, selCls, selBox, keep,
                                       (float*)d_out, out_size);
}

// round 11
// speedup vs baseline: 1.4886x; 1.4886x over previous
#include <cuda_runtime.h>
#include <math.h>

#define CDIV(a,b) (((a)+(b)-1)/(b))
#define N_ANCH 76725
#define N_SORT 131072
#define KTOP   1000
#define TS     (256*8525)
typedef unsigned long long ull;

// dynamic smem layout: wBuf[2][9216] floats, then inBuf[2][1120] ull
#define WBUF_FLOATS 9216
#define INBUF_ULLS  1120
#define DYN_SMEM (2*WBUF_FLOATS*4 + 2*INBUF_ULLS*8)   // 91648 B

// ---------------- scratch (static device globals; no allocation) -------------
__device__ float g_bufA[2*TS];
__device__ float g_bufB[2*TS];
__device__ float g_wTrunk[2*4*256*9*256];      // [tower][layer][ci][k][co]
__device__ float g_wCls[256*9*768];
__device__ float g_wReg[256*9*128];
__device__ float g_cls[720*8525];
__device__ float g_reg[36*8525];
__device__ float g_scores[N_ANCH];
__device__ int   g_arg[N_ANCH];
__device__ float4 g_loc[N_ANCH];
__device__ ull   g_keys[N_SORT];
__device__ ull   g_tmpA[32*1024];
__device__ ull   g_tmpB[16*1024];
__device__ unsigned g_mask[KTOP*32];
__device__ float4 g_selBox[KTOP];
__device__ float  g_topVal[KTOP];
__device__ int    g_selCls[KTOP];
__device__ unsigned char g_keep[KTOP];

// ---------------- fused weight transpose -------------------------------------
#define TRKN (4*256*9*256)
__global__ void transpose_all_k(const float* __restrict__ cls_w,
                                const float* __restrict__ reg_w,
                                const float* __restrict__ cls_hw,
                                const float* __restrict__ reg_hw,
                                float* __restrict__ wTrk,
                                float* __restrict__ wCls,
                                float* __restrict__ wReg)
{
    int idx = blockIdx.x * blockDim.x + threadIdx.x;
    if (idx < 2*TRKN) {
        const float* src = (idx < TRKN) ? cls_w : reg_w;
        int i = (idx < TRKN) ? idx : idx - TRKN;
        int co = i & 255, r = i >> 8;
        int kk = r % 9, r2 = r / 9;
        int ci = r2 & 255, layer = r2 >> 8;
        wTrk[idx] = src[((layer*256 + co)*256 + ci)*9 + kk];
        return;
    }
    idx -= 2*TRKN;
    if (idx < 256*9*768) {
        int co = idx % 768, r = idx / 768;
        int kk = r % 9, ci = r / 9;
        wCls[idx] = (co < 720) ? cls_hw[(co*256 + ci)*9 + kk] : 0.f;
        return;
    }
    idx -= 256*9*768;
    if (idx < 256*9*128) {
        int co = idx % 128, r = idx / 128;
        int kk = r % 9, ci = r / 9;
        wReg[idx] = (co < 36) ? reg_hw[(co*256 + ci)*9 + kk] : 0.f;
    }
}

// ---------------- helpers ----------------------------------------------------
__device__ __forceinline__ void ffma2(ull& d, ull a, ull b) {
    asm("fma.rn.f32x2 %0, %1, %2, %0;" : "+l"(d) : "l"(a), "l"(b));
}
__device__ __forceinline__ ull pack2(float v) {
    ull r; asm("mov.b64 %0, {%1, %1};" : "=l"(r) : "f"(v)); return r;
}
__device__ __forceinline__ float lo32(ull a) { return __uint_as_float((unsigned)a); }
__device__ __forceinline__ float hi32(ull a) { return __uint_as_float((unsigned)(a >> 32)); }
__device__ __forceinline__ void cp_async16(unsigned saddr, const void* gptr) {
    asm volatile("cp.async.cg.shared.global [%0], [%1], 16;" :: "r"(saddr), "l"(gptr));
}
#define CP_COMMIT() asm volatile("cp.async.commit_group;")
#define CP_WAIT0()  asm volatile("cp.async.wait_group 0;")

__device__ __forceinline__ void tile_decode(int t, int& L, int& H, int& hwBase,
                                            int& x0, int& y0)
{
    int tpr;
    if      (t < 100) { L=0; H=80; hwBase=0;    tpr=10; }
    else if (t < 125) { L=1; H=40; hwBase=6400; tpr=5;  t-=100; }
    else if (t < 134) { L=2; H=20; hwBase=8000; tpr=3;  t-=125; }
    else if (t < 138) { L=3; H=10; hwBase=8400; tpr=2;  t-=134; }
    else              { L=4; H=5;  hwBase=8500; tpr=1;  t-=138; }
    x0 = (t % tpr) * 8; y0 = (t / tpr) * 8;
}

// ---------------- conv core: pipelined, double-buffered (round-6 proven) -----
__device__ __forceinline__ void conv_core(
    const float* __restrict__ in, const float* __restrict__ wT, int STR,
    int coBase, const float* __restrict__ bias, float* __restrict__ out,
    int Cout, int relu, int H, int x0, int y0)
{
    extern __shared__ __align__(16) char dynsmem[];
    float* wBuf = (float*)dynsmem;                              // [2][9216]
    ull*   inBuf = (ull*)(dynsmem + 2*WBUF_FLOATS*4);           // [2][1120]

    const int W = H, HW = H * W;
    const int tid = threadIdx.x;
    const int p = tid & 15, q = tid >> 4;
    const int pyb = (p >> 2) * 2, pxb = (p & 3) * 2;
    const int coQ = q * 8;

    // input-tile geometry (4 items/thread, 800 total)
    int  sAddr[4]; int gInv[4]; bool okL[4], okS[4];
    #pragma unroll
    for (int j = 0; j < 4; j++) {
        int idx = tid + j * 256;
        int ci = idx / 100, r = idx % 100, dy = r / 10, dx = r % 10;
        int gy = y0 - 1 + dy, gx = x0 - 1 + dx;
        okS[j] = idx < 800;
        okL[j] = okS[j] && gy >= 0 && gy < H && gx >= 0 && gx < W;
        gInv[j] = okL[j] ? (ci * HW + gy * W + gx) : 0;
        sAddr[j] = ci * 140 + dy * 14 + dx;
    }

    // weight fill: 2304 16B-chunks, 9 per thread
    auto issueW = [&](int chunk, int bIdx) {
        const float* wp = wT + chunk * 72 * STR + coBase;
        unsigned sb = (unsigned)__cvta_generic_to_shared(wBuf + bIdx * WBUF_FLOATS);
        #pragma unroll
        for (int c = 0; c < 9; c++) {
            int i = tid + c * 256;
            int row = i >> 5, lane = i & 31;
            cp_async16(sb + row * 512 + lane * 16, wp + row * STR + lane * 4);
        }
        CP_COMMIT();
    };
    auto loadIn = [&](int chunk, float vreg[4]) {
        #pragma unroll
        for (int j = 0; j < 4; j++)
            vreg[j] = okL[j] ? __ldg(in + gInv[j] + chunk * 8 * HW) : 0.f;
    };
    auto storeIn = [&](int bIdx, const float vreg[4]) {
        #pragma unroll
        for (int j = 0; j < 4; j++)
            if (okS[j]) inBuf[bIdx * INBUF_ULLS + sAddr[j]] = pack2(vreg[j]);
    };

    // prologue: chunk 0 into buffer 0
    {
        float v0[4];
        issueW(0, 0);
        loadIn(0, v0);
        storeIn(0, v0);
        CP_WAIT0();
    }
    __syncthreads();

    ull acc[2][2][4] = {};

    #pragma unroll 1
    for (int chunk = 0; chunk < 32; chunk++) {
        const int cur = chunk & 1;
        const bool more = (chunk + 1) < 32;
        float vnext[4];
        if (more) { issueW(chunk + 1, cur ^ 1); loadIn(chunk + 1, vnext); }

        const float* s_w = wBuf + cur * WBUF_FLOATS;
        const ull* s_base = inBuf + cur * INBUF_ULLS;

        #pragma unroll 1
        for (int ci = 0; ci < 8; ci++) {
            const ull* rowb = s_base + ci * 140;
            const float* wcb = s_w + ci * 9 * 128 + coQ;
            ull iv[4][4];
            #pragma unroll
            for (int r = 0; r < 4; r++) {
                const ulonglong2* rp = (const ulonglong2*)(rowb + (pyb + r) * 14 + pxb);
                ulonglong2 v0 = rp[0], v1 = rp[1];
                iv[r][0] = v0.x; iv[r][1] = v0.y; iv[r][2] = v1.x; iv[r][3] = v1.y;
            }
            #pragma unroll
            for (int ky = 0; ky < 3; ky++) {
                #pragma unroll
                for (int kx = 0; kx < 3; kx++) {
                    const float* wrow = wcb + (ky * 3 + kx) * 128;
                    ulonglong2 wa = *(const ulonglong2*)(wrow);
                    ulonglong2 wb = *(const ulonglong2*)(wrow + 4);
                    #pragma unroll
                    for (int py = 0; py < 2; py++)
                        #pragma unroll
                        for (int px = 0; px < 2; px++) {
                            ull v = iv[ky + py][px + kx];
                            ffma2(acc[py][px][0], v, wa.x);
                            ffma2(acc[py][px][1], v, wa.y);
                            ffma2(acc[py][px][2], v, wb.x);
                            ffma2(acc[py][px][3], v, wb.y);
                        }
                }
            }
        }

        if (more) { storeIn(cur ^ 1, vnext); CP_WAIT0(); }
        __syncthreads();
    }

    #pragma unroll
    for (int pr = 0; pr < 4; pr++) {
        int c0 = coBase + coQ + pr * 2, c1 = c0 + 1;
        if (c0 >= Cout) continue;
        float b0 = bias[c0];
        float b1 = (c1 < Cout) ? bias[c1] : 0.f;
        #pragma unroll
        for (int py = 0; py < 2; py++) {
            int y = y0 + pyb + py;
            if (y >= H) continue;
            #pragma unroll
            for (int px = 0; px < 2; px++) {
                int x = x0 + pxb + px;
                if (x >= W) continue;
                float v0 = lo32(acc[py][px][pr]) + b0;
                float v1 = hi32(acc[py][px][pr]) + b1;
                if (relu) { v0 = fmaxf(v0, 0.f); v1 = fmaxf(v1, 0.f); }
                out[c0 * HW + y * W + x] = v0;
                if (c1 < Cout) out[c1 * HW + y * W + x] = v1;
            }
        }
    }
}

__global__ __launch_bounds__(256, 2)
void conv_trunk_k(const float* f0, const float* f1, const float* f2,
                  const float* f3, const float* f4,
                  const float* __restrict__ actIn, float* __restrict__ actOut,
                  const float* __restrict__ wT,
                  const float* __restrict__ biasCls, const float* __restrict__ biasReg,
                  int layer, int isFirst)
{
    int L, H, hwBase, x0, y0;
    tile_decode(blockIdx.x, L, H, hwBase, x0, y0);
    const int tower = blockIdx.z;
    const int coBase = blockIdx.y * 128;
    const float* in;
    if (isFirst) {
        const float* fs[5] = {f0, f1, f2, f3, f4};
        in = fs[L];
    } else {
        in = actIn + tower * TS + hwBase * 256;
    }
    const float* w = wT + (tower * 4 + layer) * (256*9*256);
    const float* b = (tower ? biasReg : biasCls) + layer * 256;
    float* out = actOut + tower * TS + hwBase * 256;
    conv_core(in, w, 256, coBase, b, out, 256, 1, H, x0, y0);
}

__global__ __launch_bounds__(256, 2)
void conv_head_k(const float* __restrict__ actIn,
                 float* __restrict__ outCls, float* __restrict__ outReg,
                 const float* __restrict__ wTc, const float* __restrict__ wTr,
                 const float* __restrict__ biasC, const float* __restrict__ biasR)
{
    int L, H, hwBase, x0, y0;
    tile_decode(blockIdx.x, L, H, hwBase, x0, y0);
    const int yy = blockIdx.y;
    if (yy < 6) {
        const float* in = actIn + 0 * TS + hwBase * 256;
        conv_core(in, wTc, 768, yy * 128, biasC, outCls + 720 * hwBase, 720, 0, H, x0, y0);
    } else {
        const float* in = actIn + 1 * TS + hwBase * 256;
        conv_core(in, wTr, 128, 0, biasR, outReg + 36 * hwBase, 36, 0, H, x0, y0);
    }
}

// ---------------- fused scores/argmax/keys + block-local sort ----------------
__global__ __launch_bounds__(1024)
void score_key_sort_k(const float* __restrict__ cls_raw,
                      const float* __restrict__ reg_raw,
                      float* __restrict__ scores, int* __restrict__ arg,
                      float4* __restrict__ loc,
                      ull* __restrict__ keys)
{
    __shared__ ull s[2048];
    int tid = threadIdx.x;

    #pragma unroll
    for (int h = 0; h < 2; h++) {
        int t = blockIdx.x * 2048 + tid + h * 1024;
        ull key = 0xFFFFFFFFFFFFFFFFULL;
        if (t < N_ANCH) {
            int L, a, p, HW, cum;
            if      (t < 57600) { L=0; int rel=t;       HW=6400; a=rel/6400; p=rel%6400; cum=0;    }
            else if (t < 72000) { L=1; int rel=t-57600; HW=1600; a=rel/1600; p=rel%1600; cum=6400; }
            else if (t < 75600) { L=2; int rel=t-72000; HW=400;  a=rel/400;  p=rel%400;  cum=8000; }
            else if (t < 76500) { L=3; int rel=t-75600; HW=100;  a=rel/100;  p=rel%100;  cum=8400; }
            else                { L=4; int rel=t-76500; HW=25;   a=rel/25;   p=rel%25;   cum=8500; }
            const int aoff[5] = {0, 57600, 72000, 75600, 76500};
            int idx = aoff[L] + p * 9 + a;

            const float* cb = cls_raw + 720 * cum + (a * 80) * HW + p;
            float best = 1.f / (1.f + expf(-cb[0]));
            int barg = 0;
            for (int c = 1; c < 80; c++) {
                float sg = 1.f / (1.f + expf(-cb[c * HW]));
                if (sg > best) { best = sg; barg = c; }
            }
            float masked = (best > 0.05f) ? best : -1.0f;
            scores[idx] = masked;
            arg[idx] = barg;

            const float* rb = reg_raw + 36 * cum + (a * 4) * HW + p;
            loc[idx] = make_float4(rb[0], rb[HW], rb[2 * HW], rb[3 * HW]);

            unsigned u = __float_as_uint(masked);
            u = (u & 0x80000000u) ? ~u : (u | 0x80000000u);
            key = (((ull)(~u)) << 32) | (unsigned)idx;
        }
        s[tid + h * 1024] = key;
    }
    __syncthreads();

    for (int k = 2; k <= 2048; k <<= 1) {
        for (int j = k >> 1; j >= 1; j >>= 1) {
            #pragma unroll
            for (int h = 0; h < 2; h++) {
                int l = tid + h * 1024;
                int ixj = l ^ j;
                if (ixj > l) {
                    ull a = s[l], b = s[ixj];
                    bool up = ((l & k) == 0);
                    if ((a > b) == up) { s[l] = b; s[ixj] = a; }
                }
            }
            __syncthreads();
        }
    }
    keys[blockIdx.x * 2048 + tid] = s[tid];
    keys[blockIdx.x * 2048 + tid + 1024] = s[tid + 1024];
}

// ---------------- tournament merge: 2 sorted-1024 lists -> best 1024 ---------
__global__ __launch_bounds__(512)
void topk_merge_k(const ull* __restrict__ in, ull* __restrict__ out, int inStride)
{
    __shared__ ull s[2048];
    int t = threadIdx.x;
    const ull* A = in + (size_t)blockIdx.x * 2 * inStride;
    const ull* B = A + inStride;
    #pragma unroll
    for (int i = t; i < 1024; i += 512) {
        s[i] = A[i];
        s[2047 - i] = B[i];
    }
    __syncthreads();
    for (int j = 1024; j >= 1; j >>= 1) {
        #pragma unroll
        for (int h = 0; h < 4; h++) {
            int l = t + h * 512;
            int ixj = l ^ j;
            if (ixj > l) {
                ull a = s[l], b = s[ixj];
                if (a > b) { s[l] = b; s[ixj] = a; }
            }
        }
        __syncthreads();
    }
    #pragma unroll
    for (int i = t; i < 1024; i += 512)
        out[blockIdx.x * 1024 + i] = s[i];
}

// ---------------- decode top-1000 boxes --------------------------------------
__device__ __forceinline__ void anchor_split(int idx, int& L, int& p, int& a, int& Wd)
{
    const int aoff[6] = {0, 57600, 72000, 75600, 76500, 76725};
    const int Ws[5] = {80, 40, 20, 10, 5};
    L = 0;
    while (L < 4 && idx >= aoff[L + 1]) L++;
    int rel = idx - aoff[L];
    p = rel / 9; a = rel - p * 9; Wd = Ws[L];
}

__global__ void decode_k(const ull* __restrict__ keys,
                         const float* __restrict__ scores,
                         const int* __restrict__ arg,
                         const float4* __restrict__ loc,
                         float4* __restrict__ selBox, float* __restrict__ topVal,
                         int* __restrict__ selCls)
{
    int r = blockIdx.x * blockDim.x + threadIdx.x;
    if (r >= KTOP) return;
    int idx = (int)(keys[r] & 0xFFFFFFFFULL);
    float val = scores[idx];
    topVal[r] = val;
    selCls[r] = arg[idx];

    const int strides[5] = {8, 16, 32, 64, 128};
    const int sizes[5] = {32, 64, 128, 256, 512};
    int L, p, a, W;
    anchor_split(idx, L, p, a, W);
    int y = p / W, x = p - y * W;
    int ri = a / 3, si = a - ri * 3;
    const float ratios[3] = {0.5f, 1.0f, 2.0f};
    const float scales[3] = {1.0f, 1.2599210498948732f, 1.5874010519681994f};
    float sq = sqrtf(ratios[ri]);
    float ws = (float)sizes[L] * scales[si] / sq;
    float hs = (float)sizes[L] * scales[si] * sq;
    float st = (float)strides[L];
    float cx = ((float)x + 0.5f) * st;
    float cy = ((float)y + 0.5f) * st;

    float4 l = loc[idx];
    float dx = l.x * 0.1f, dy = l.y * 0.1f, dw = l.z * 0.2f, dh = l.w * 0.2f;
    float pcx = cx + dx * ws, pcy = cy + dy * hs;
    float pw = expf(dw) * ws, ph = expf(dh) * hs;
    float bx1 = fminf(fmaxf(pcx - 0.5f * pw, 0.f), 640.f);
    float by1 = fminf(fmaxf(pcy - 0.5f * ph, 0.f), 640.f);
    float bx2 = fminf(fmaxf(pcx + 0.5f * pw, 0.f), 640.f);
    float by2 = fminf(fmaxf(pcy + 0.5f * ph, 0.f), 640.f);
    selBox[r] = make_float4(bx1, by1, bx2, by2);
}

// ---------------- NMS --------------------------------------------------------
__global__ __launch_bounds__(1024)
void iou_mask_k(const float4* __restrict__ boxes, unsigned* __restrict__ mask)
{
    int i = blockIdx.x;
    int j = threadIdx.x;
    float4 bi = boxes[i];
    float4 bj = (j < KTOP) ? boxes[j] : make_float4(0,0,0,0);
    float ai = fmaxf(bi.z - bi.x, 0.f) * fmaxf(bi.w - bi.y, 0.f);
    float aj = fmaxf(bj.z - bj.x, 0.f) * fmaxf(bj.w - bj.y, 0.f);
    float xx1 = fmaxf(bi.x, bj.x), yy1 = fmaxf(bi.y, bj.y);
    float xx2 = fminf(bi.z, bj.z), yy2 = fminf(bi.w, bj.w);
    float inter = fmaxf(xx2 - xx1, 0.f) * fmaxf(yy2 - yy1, 0.f);
    float iou = inter / (ai + aj - inter + 1e-8f);
    bool sup = (j < KTOP) && (j > i) && (iou > 0.5f);
    unsigned bal = __ballot_sync(0xffffffffu, sup);
    if ((j & 31) == 0) mask[i * 32 + (j >> 5)] = bal;
}

__global__ void nms_seq_k(const unsigned* __restrict__ mask,
                          const float* __restrict__ vals,
                          unsigned char* __restrict__ keepOut)
{
    int lane = threadIdx.x;
    unsigned validw = 0;
    #pragma unroll
    for (int b = 0; b < 32; b++) {
        int j = lane * 32 + b;
        if (j < KTOP && vals[j] > 0.f) validw |= (1u << b);
    }
    unsigned remv = 0;
    for (int i = 0; i < KTOP; i++) {
        unsigned row = mask[i * 32 + lane];
        unsigned rm = __shfl_sync(0xffffffffu, remv, i >> 5);
        unsigned vw = __shfl_sync(0xffffffffu, validw, i >> 5);
        unsigned bi = i & 31;
        if (((vw >> bi) & 1) && !((rm >> bi) & 1))
            remv |= row;
    }
    #pragma unroll
    for (int b = 0; b < 32; b++) {
        int j = lane * 32 + b;
        if (j < KTOP)
            keepOut[j] = (unsigned char)(((validw >> b) & 1) && !((remv >> b) & 1));
    }
}

// ---------------- pack output ------------------------------------------------
__global__ void output_k(const float* __restrict__ vals, const int* __restrict__ cls,
                         const float4* __restrict__ boxes,
                         const unsigned char* __restrict__ keep,
                         float* __restrict__ out, int out_size)
{
    int r = blockIdx.x * blockDim.x + threadIdx.x;
    if (r >= KTOP) return;
    bool k = keep[r] != 0;
    float4 b = boxes[r];
    if (r < out_size) out[r] = k ? vals[r] : 0.f;
    if (1000 + r < out_size) out[1000 + r] = (float)cls[r];
    if (2000 + 4 * r + 3 < out_size) {
        out[2000 + 4 * r + 0] = k ? b.x : 0.f;
        out[2000 + 4 * r + 1] = k ? b.y : 0.f;
        out[2000 + 4 * r + 2] = k ? b.z : 0.f;
        out[2000 + 4 * r + 3] = k ? b.w : 0.f;
    }
    if (6000 + r < out_size) out[6000 + r] = k ? 1.f : 0.f;
}

// ---------------- host orchestration -----------------------------------------
extern "C" void kernel_launch(void* const* d_in, const int* in_sizes, int n_in,
                              void* d_out, int out_size)
{
    (void)in_sizes; (void)n_in;
    const float* f0 = (const float*)d_in[0];
    const float* f1 = (const float*)d_in[1];
    const float* f2 = (const float*)d_in[2];
    const float* f3 = (const float*)d_in[3];
    const float* f4 = (const float*)d_in[4];
    const float* cls_w  = (const float*)d_in[5];
    const float* cls_b  = (const float*)d_in[6];
    const float* cls_hw = (const float*)d_in[7];
    const float* cls_hb = (const float*)d_in[8];
    const float* reg_w  = (const float*)d_in[9];
    const float* reg_b  = (const float*)d_in[10];
    const float* reg_hw = (const float*)d_in[11];
    const float* reg_hb = (const float*)d_in[12];

    float *bufA, *bufB, *wTrk, *wCls, *wReg, *clsR, *regR, *scores, *topVal;
    int *arg, *selCls;
    float4 *loc, *selBox;
    ull *keys, *tmpA, *tmpB;
    unsigned *mask;
    unsigned char* keep;
    cudaGetSymbolAddress((void**)&bufA, g_bufA);
    cudaGetSymbolAddress((void**)&bufB, g_bufB);
    cudaGetSymbolAddress((void**)&wTrk, g_wTrunk);
    cudaGetSymbolAddress((void**)&wCls, g_wCls);
    cudaGetSymbolAddress((void**)&wReg, g_wReg);
    cudaGetSymbolAddress((void**)&clsR, g_cls);
    cudaGetSymbolAddress((void**)&regR, g_reg);
    cudaGetSymbolAddress((void**)&scores, g_scores);
    cudaGetSymbolAddress((void**)&arg, g_arg);
    cudaGetSymbolAddress((void**)&loc, g_loc);
    cudaGetSymbolAddress((void**)&keys, g_keys);
    cudaGetSymbolAddress((void**)&tmpA, g_tmpA);
    cudaGetSymbolAddress((void**)&tmpB, g_tmpB);
    cudaGetSymbolAddress((void**)&mask, g_mask);
    cudaGetSymbolAddress((void**)&selBox, g_selBox);
    cudaGetSymbolAddress((void**)&topVal, g_topVal);
    cudaGetSymbolAddress((void**)&selCls, g_selCls);
    cudaGetSymbolAddress((void**)&keep, g_keep);

    static int smemSet = 0;
    if (!smemSet) {
        cudaFuncSetAttribute(conv_trunk_k, cudaFuncAttributeMaxDynamicSharedMemorySize, DYN_SMEM);
        cudaFuncSetAttribute(conv_head_k,  cudaFuncAttributeMaxDynamicSharedMemorySize, DYN_SMEM);
        smemSet = 1;
    }

    const int TOTW = 2*TRKN + 256*9*768 + 256*9*128;
    transpose_all_k<<<CDIV(TOTW,256), 256>>>(cls_w, reg_w, cls_hw, reg_hw, wTrk, wCls, wReg);

    dim3 gt(139, 2, 2);
    conv_trunk_k<<<gt, 256, DYN_SMEM>>>(f0,f1,f2,f3,f4, nullptr, bufA, wTrk, cls_b, reg_b, 0, 1);
    conv_trunk_k<<<gt, 256, DYN_SMEM>>>(f0,f1,f2,f3,f4, bufA,    bufB, wTrk, cls_b, reg_b, 1, 0);
    conv_trunk_k<<<gt, 256, DYN_SMEM>>>(f0,f1,f2,f3,f4, bufB,    bufA, wTrk, cls_b, reg_b, 2, 0);
    conv_trunk_k<<<gt, 256, DYN_SMEM>>>(f0,f1,f2,f3,f4, bufA,    bufB, wTrk, cls_b, reg_b, 3, 0);
    dim3 gh(139, 7, 1);
    conv_head_k<<<gh, 256, DYN_SMEM>>>(bufB, clsR, regR, wCls, wReg, cls_hb, reg_hb);

    score_key_sort_k<<<N_SORT / 2048, 1024>>>(clsR, regR, scores, arg, loc, keys);

    topk_merge_k<<<32, 512>>>(keys, tmpA, 2048);
    topk_merge_k<<<16, 512>>>(tmpA, tmpB, 1024);
    topk_merge_k<<< 8, 512>>>(tmpB, tmpA, 1024);
    topk_merge_k<<< 4, 512>>>(tmpA, tmpB, 1024);
    topk_merge_k<<< 2, 512>>>(tmpB, tmpA, 1024);
    topk_merge_k<<< 1, 512>>>(tmpA, tmpB, 1024);

    decode_k<<<CDIV(KTOP, 256), 256>>>(tmpB, scores, arg, loc, selBox, topVal, selCls);
    iou_mask_k<<<KTOP, 1024>>>(selBox, mask);
    nms_seq_k<<<1, 32>>>(mask, topVal, keep);
    output_k<<<CDIV(KTOP, 256), 256>>>(topVal, selCls, selBox, keep,
                                       (float*)d_out, out_size);
}

// round 12
// speedup vs baseline: 1.6460x; 1.1057x over previous
#include <cuda_runtime.h>
#include <math.h>

#define CDIV(a,b) (((a)+(b)-1)/(b))
#define N_ANCH 76725
#define N_SORT 131072
#define KTOP   1000
#define TS     (256*8525)
typedef unsigned long long ull;

// dynamic smem layout: wBuf[2][9216] floats, then inBuf[2][1120] floats (de-duplicated)
#define WBUF_FLOATS 9216
#define INBUF_FLOATS 1120
#define DYN_SMEM (2*WBUF_FLOATS*4 + 2*INBUF_FLOATS*4)   // 73728 + 8960 = 82688 B

// ---------------- scratch (static device globals; no allocation) -------------
__device__ float g_bufA[2*TS];
__device__ float g_bufB[2*TS];
__device__ float g_wTrunk[2*4*256*9*256];      // [tower][layer][ci][k][co]
__device__ float g_wCls[256*9*768];
__device__ float g_wReg[256*9*128];
__device__ float g_cls[720*8525];
__device__ float g_reg[36*8525];
__device__ float g_scores[N_ANCH];
__device__ int   g_arg[N_ANCH];
__device__ float4 g_loc[N_ANCH];
__device__ ull   g_keys[N_SORT];
__device__ ull   g_tmpA[32*1024];
__device__ ull   g_tmpB[16*1024];
__device__ unsigned g_mask[KTOP*32];
__device__ float4 g_selBox[KTOP];
__device__ float  g_topVal[KTOP];
__device__ int    g_selCls[KTOP];
__device__ unsigned char g_keep[KTOP];

// ---------------- fused weight transpose -------------------------------------
#define TRKN (4*256*9*256)
__global__ void transpose_all_k(const float* __restrict__ cls_w,
                                const float* __restrict__ reg_w,
                                const float* __restrict__ cls_hw,
                                const float* __restrict__ reg_hw,
                                float* __restrict__ wTrk,
                                float* __restrict__ wCls,
                                float* __restrict__ wReg)
{
    int idx = blockIdx.x * blockDim.x + threadIdx.x;
    if (idx < 2*TRKN) {
        const float* src = (idx < TRKN) ? cls_w : reg_w;
        int i = (idx < TRKN) ? idx : idx - TRKN;
        int co = i & 255, r = i >> 8;
        int kk = r % 9, r2 = r / 9;
        int ci = r2 & 255, layer = r2 >> 8;
        wTrk[idx] = src[((layer*256 + co)*256 + ci)*9 + kk];
        return;
    }
    idx -= 2*TRKN;
    if (idx < 256*9*768) {
        int co = idx % 768, r = idx / 768;
        int kk = r % 9, ci = r / 9;
        wCls[idx] = (co < 720) ? cls_hw[(co*256 + ci)*9 + kk] : 0.f;
        return;
    }
    idx -= 256*9*768;
    if (idx < 256*9*128) {
        int co = idx % 128, r = idx / 128;
        int kk = r % 9, ci = r / 9;
        wReg[idx] = (co < 36) ? reg_hw[(co*256 + ci)*9 + kk] : 0.f;
    }
}

// ---------------- helpers ----------------------------------------------------
__device__ __forceinline__ void ffma2(ull& d, ull a, ull b) {
    asm("fma.rn.f32x2 %0, %1, %2, %0;" : "+l"(d) : "l"(a), "l"(b));
}
__device__ __forceinline__ ull pack2(float v) {
    ull r; asm("mov.b64 %0, {%1, %1};" : "=l"(r) : "f"(v)); return r;
}
__device__ __forceinline__ float lo32(ull a) { return __uint_as_float((unsigned)a); }
__device__ __forceinline__ float hi32(ull a) { return __uint_as_float((unsigned)(a >> 32)); }
__device__ __forceinline__ void cp_async16(unsigned saddr, const void* gptr) {
    asm volatile("cp.async.cg.shared.global [%0], [%1], 16;" :: "r"(saddr), "l"(gptr));
}
#define CP_COMMIT() asm volatile("cp.async.commit_group;")
#define CP_WAIT0()  asm volatile("cp.async.wait_group 0;")

__device__ __forceinline__ void tile_decode(int t, int& L, int& H, int& hwBase,
                                            int& x0, int& y0)
{
    int tpr;
    if      (t < 100) { L=0; H=80; hwBase=0;    tpr=10; }
    else if (t < 125) { L=1; H=40; hwBase=6400; tpr=5;  t-=100; }
    else if (t < 134) { L=2; H=20; hwBase=8000; tpr=3;  t-=125; }
    else if (t < 138) { L=3; H=10; hwBase=8400; tpr=2;  t-=134; }
    else              { L=4; H=5;  hwBase=8500; tpr=1;  t-=138; }
    x0 = (t % tpr) * 8; y0 = (t / tpr) * 8;
}

// ---------------- conv core: pipelined, double-buffered, de-dup input --------
__device__ __forceinline__ void conv_core(
    const float* __restrict__ in, const float* __restrict__ wT, int STR,
    int coBase, const float* __restrict__ bias, float* __restrict__ out,
    int Cout, int relu, int H, int x0, int y0)
{
    extern __shared__ __align__(16) char dynsmem[];
    float* wBuf = (float*)dynsmem;                              // [2][9216]
    float* inBuf = (float*)(dynsmem + 2*WBUF_FLOATS*4);         // [2][1120]

    const int W = H, HW = H * W;
    const int tid = threadIdx.x;
    const int p = tid & 15, q = tid >> 4;
    const int pyb = (p >> 2) * 2, pxb = (p & 3) * 2;
    const int coQ = q * 8;

    // input-tile geometry (4 items/thread, 800 total)
    int  sAddr[4]; int gInv[4]; bool okL[4], okS[4];
    #pragma unroll
    for (int j = 0; j < 4; j++) {
        int idx = tid + j * 256;
        int ci = idx / 100, r = idx % 100, dy = r / 10, dx = r % 10;
        int gy = y0 - 1 + dy, gx = x0 - 1 + dx;
        okS[j] = idx < 800;
        okL[j] = okS[j] && gy >= 0 && gy < H && gx >= 0 && gx < W;
        gInv[j] = okL[j] ? (ci * HW + gy * W + gx) : 0;
        sAddr[j] = ci * 140 + dy * 14 + dx;
    }

    // weight fill: 2304 16B-chunks, 9 per thread
    auto issueW = [&](int chunk, int bIdx) {
        const float* wp = wT + chunk * 72 * STR + coBase;
        unsigned sb = (unsigned)__cvta_generic_to_shared(wBuf + bIdx * WBUF_FLOATS);
        #pragma unroll
        for (int c = 0; c < 9; c++) {
            int i = tid + c * 256;
            int row = i >> 5, lane = i & 31;
            cp_async16(sb + row * 512 + lane * 16, wp + row * STR + lane * 4);
        }
        CP_COMMIT();
    };
    auto loadIn = [&](int chunk, float vreg[4]) {
        #pragma unroll
        for (int j = 0; j < 4; j++)
            vreg[j] = okL[j] ? __ldg(in + gInv[j] + chunk * 8 * HW) : 0.f;
    };
    auto storeIn = [&](int bIdx, const float vreg[4]) {
        #pragma unroll
        for (int j = 0; j < 4; j++)
            if (okS[j]) inBuf[bIdx * INBUF_FLOATS + sAddr[j]] = vreg[j];
    };

    // prologue: chunk 0 into buffer 0
    {
        float v0[4];
        issueW(0, 0);
        loadIn(0, v0);
        storeIn(0, v0);
        CP_WAIT0();
    }
    __syncthreads();

    ull acc[2][2][4] = {};

    #pragma unroll 1
    for (int chunk = 0; chunk < 32; chunk++) {
        const int cur = chunk & 1;
        const bool more = (chunk + 1) < 32;
        float vnext[4];
        if (more) { issueW(chunk + 1, cur ^ 1); loadIn(chunk + 1, vnext); }

        const float* s_w = wBuf + cur * WBUF_FLOATS;
        const float* s_base = inBuf + cur * INBUF_FLOATS;

        #pragma unroll 1
        for (int ci = 0; ci < 8; ci++) {
            const float* rowb = s_base + ci * 140;
            const float* wcb = s_w + ci * 9 * 128 + coQ;
            // 4 rows x 4 cols of input, loaded as aligned LDS.64 pairs and
            // duplicated into (v,v) f32x2 operands via MOV.64 (ALU pipe).
            ull iv[4][4];
            #pragma unroll
            for (int r = 0; r < 4; r++) {
                const float2* rp = (const float2*)(rowb + (pyb + r) * 14 + pxb);
                float2 v0 = rp[0], v1 = rp[1];
                iv[r][0] = pack2(v0.x); iv[r][1] = pack2(v0.y);
                iv[r][2] = pack2(v1.x); iv[r][3] = pack2(v1.y);
            }
            #pragma unroll
            for (int ky = 0; ky < 3; ky++) {
                #pragma unroll
                for (int kx = 0; kx < 3; kx++) {
                    const float* wrow = wcb + (ky * 3 + kx) * 128;
                    ulonglong2 wa = *(const ulonglong2*)(wrow);
                    ulonglong2 wb = *(const ulonglong2*)(wrow + 4);
                    #pragma unroll
                    for (int py = 0; py < 2; py++)
                        #pragma unroll
                        for (int px = 0; px < 2; px++) {
                            ull v = iv[ky + py][px + kx];
                            ffma2(acc[py][px][0], v, wa.x);
                            ffma2(acc[py][px][1], v, wa.y);
                            ffma2(acc[py][px][2], v, wb.x);
                            ffma2(acc[py][px][3], v, wb.y);
                        }
                }
            }
        }

        if (more) { storeIn(cur ^ 1, vnext); CP_WAIT0(); }
        __syncthreads();
    }

    #pragma unroll
    for (int pr = 0; pr < 4; pr++) {
        int c0 = coBase + coQ + pr * 2, c1 = c0 + 1;
        if (c0 >= Cout) continue;
        float b0 = bias[c0];
        float b1 = (c1 < Cout) ? bias[c1] : 0.f;
        #pragma unroll
        for (int py = 0; py < 2; py++) {
            int y = y0 + pyb + py;
            if (y >= H) continue;
            #pragma unroll
            for (int px = 0; px < 2; px++) {
                int x = x0 + pxb + px;
                if (x >= W) continue;
                float v0 = lo32(acc[py][px][pr]) + b0;
                float v1 = hi32(acc[py][px][pr]) + b1;
                if (relu) { v0 = fmaxf(v0, 0.f); v1 = fmaxf(v1, 0.f); }
                out[c0 * HW + y * W + x] = v0;
                if (c1 < Cout) out[c1 * HW + y * W + x] = v1;
            }
        }
    }
}

__global__ __launch_bounds__(256, 2)
void conv_trunk_k(const float* f0, const float* f1, const float* f2,
                  const float* f3, const float* f4,
                  const float* __restrict__ actIn, float* __restrict__ actOut,
                  const float* __restrict__ wT,
                  const float* __restrict__ biasCls, const float* __restrict__ biasReg,
                  int layer, int isFirst)
{
    int L, H, hwBase, x0, y0;
    tile_decode(blockIdx.x, L, H, hwBase, x0, y0);
    const int tower = blockIdx.z;
    const int coBase = blockIdx.y * 128;
    const float* in;
    if (isFirst) {
        const float* fs[5] = {f0, f1, f2, f3, f4};
        in = fs[L];
    } else {
        in = actIn + tower * TS + hwBase * 256;
    }
    const float* w = wT + (tower * 4 + layer) * (256*9*256);
    const float* b = (tower ? biasReg : biasCls) + layer * 256;
    float* out = actOut + tower * TS + hwBase * 256;
    conv_core(in, w, 256, coBase, b, out, 256, 1, H, x0, y0);
}

__global__ __launch_bounds__(256, 2)
void conv_head_k(const float* __restrict__ actIn,
                 float* __restrict__ outCls, float* __restrict__ outReg,
                 const float* __restrict__ wTc, const float* __restrict__ wTr,
                 const float* __restrict__ biasC, const float* __restrict__ biasR)
{
    int L, H, hwBase, x0, y0;
    tile_decode(blockIdx.x, L, H, hwBase, x0, y0);
    const int yy = blockIdx.y;
    if (yy < 6) {
        const float* in = actIn + 0 * TS + hwBase * 256;
        conv_core(in, wTc, 768, yy * 128, biasC, outCls + 720 * hwBase, 720, 0, H, x0, y0);
    } else {
        const float* in = actIn + 1 * TS + hwBase * 256;
        conv_core(in, wTr, 128, 0, biasR, outReg + 36 * hwBase, 36, 0, H, x0, y0);
    }
}

// ---------------- fused scores/argmax/keys + block-local sort ----------------
__global__ __launch_bounds__(1024)
void score_key_sort_k(const float* __restrict__ cls_raw,
                      const float* __restrict__ reg_raw,
                      float* __restrict__ scores, int* __restrict__ arg,
                      float4* __restrict__ loc,
                      ull* __restrict__ keys)
{
    __shared__ ull s[2048];
    int tid = threadIdx.x;

    #pragma unroll
    for (int h = 0; h < 2; h++) {
        int t = blockIdx.x * 2048 + tid + h * 1024;
        ull key = 0xFFFFFFFFFFFFFFFFULL;
        if (t < N_ANCH) {
            int L, a, p, HW, cum;
            if      (t < 57600) { L=0; int rel=t;       HW=6400; a=rel/6400; p=rel%6400; cum=0;    }
            else if (t < 72000) { L=1; int rel=t-57600; HW=1600; a=rel/1600; p=rel%1600; cum=6400; }
            else if (t < 75600) { L=2; int rel=t-72000; HW=400;  a=rel/400;  p=rel%400;  cum=8000; }
            else if (t < 76500) { L=3; int rel=t-75600; HW=100;  a=rel/100;  p=rel%100;  cum=8400; }
            else                { L=4; int rel=t-76500; HW=25;   a=rel/25;   p=rel%25;   cum=8500; }
            const int aoff[5] = {0, 57600, 72000, 75600, 76500};
            int idx = aoff[L] + p * 9 + a;

            const float* cb = cls_raw + 720 * cum + (a * 80) * HW + p;
            float best = 1.f / (1.f + expf(-cb[0]));
            int barg = 0;
            for (int c = 1; c < 80; c++) {
                float sg = 1.f / (1.f + expf(-cb[c * HW]));
                if (sg > best) { best = sg; barg = c; }
            }
            float masked = (best > 0.05f) ? best : -1.0f;
            scores[idx] = masked;
            arg[idx] = barg;

            const float* rb = reg_raw + 36 * cum + (a * 4) * HW + p;
            loc[idx] = make_float4(rb[0], rb[HW], rb[2 * HW], rb[3 * HW]);

            unsigned u = __float_as_uint(masked);
            u = (u & 0x80000000u) ? ~u : (u | 0x80000000u);
            key = (((ull)(~u)) << 32) | (unsigned)idx;
        }
        s[tid + h * 1024] = key;
    }
    __syncthreads();

    for (int k = 2; k <= 2048; k <<= 1) {
        for (int j = k >> 1; j >= 1; j >>= 1) {
            #pragma unroll
            for (int h = 0; h < 2; h++) {
                int l = tid + h * 1024;
                int ixj = l ^ j;
                if (ixj > l) {
                    ull a = s[l], b = s[ixj];
                    bool up = ((l & k) == 0);
                    if ((a > b) == up) { s[l] = b; s[ixj] = a; }
                }
            }
            __syncthreads();
        }
    }
    keys[blockIdx.x * 2048 + tid] = s[tid];
    keys[blockIdx.x * 2048 + tid + 1024] = s[tid + 1024];
}

// ---------------- tournament merge: 2 sorted-1024 lists -> best 1024 ---------
__global__ __launch_bounds__(512)
void topk_merge_k(const ull* __restrict__ in, ull* __restrict__ out, int inStride)
{
    __shared__ ull s[2048];
    int t = threadIdx.x;
    const ull* A = in + (size_t)blockIdx.x * 2 * inStride;
    const ull* B = A + inStride;
    #pragma unroll
    for (int i = t; i < 1024; i += 512) {
        s[i] = A[i];
        s[2047 - i] = B[i];
    }
    __syncthreads();
    for (int j = 1024; j >= 1; j >>= 1) {
        #pragma unroll
        for (int h = 0; h < 4; h++) {
            int l = t + h * 512;
            int ixj = l ^ j;
            if (ixj > l) {
                ull a = s[l], b = s[ixj];
                if (a > b) { s[l] = b; s[ixj] = a; }
            }
        }
        __syncthreads();
    }
    #pragma unroll
    for (int i = t; i < 1024; i += 512)
        out[blockIdx.x * 1024 + i] = s[i];
}

// ---------------- decode top-1000 boxes --------------------------------------
__device__ __forceinline__ void anchor_split(int idx, int& L, int& p, int& a, int& Wd)
{
    const int aoff[6] = {0, 57600, 72000, 75600, 76500, 76725};
    const int Ws[5] = {80, 40, 20, 10, 5};
    L = 0;
    while (L < 4 && idx >= aoff[L + 1]) L++;
    int rel = idx - aoff[L];
    p = rel / 9; a = rel - p * 9; Wd = Ws[L];
}

__global__ void decode_k(const ull* __restrict__ keys,
                         const float* __restrict__ scores,
                         const int* __restrict__ arg,
                         const float4* __restrict__ loc,
                         float4* __restrict__ selBox, float* __restrict__ topVal,
                         int* __restrict__ selCls)
{
    int r = blockIdx.x * blockDim.x + threadIdx.x;
    if (r >= KTOP) return;
    int idx = (int)(keys[r] & 0xFFFFFFFFULL);
    float val = scores[idx];
    topVal[r] = val;
    selCls[r] = arg[idx];

    const int strides[5] = {8, 16, 32, 64, 128};
    const int sizes[5] = {32, 64, 128, 256, 512};
    int L, p, a, W;
    anchor_split(idx, L, p, a, W);
    int y = p / W, x = p - y * W;
    int ri = a / 3, si = a - ri * 3;
    const float ratios[3] = {0.5f, 1.0f, 2.0f};
    const float scales[3] = {1.0f, 1.2599210498948732f, 1.5874010519681994f};
    float sq = sqrtf(ratios[ri]);
    float ws = (float)sizes[L] * scales[si] / sq;
    float hs = (float)sizes[L] * scales[si] * sq;
    float st = (float)strides[L];
    float cx = ((float)x + 0.5f) * st;
    float cy = ((float)y + 0.5f) * st;

    float4 l = loc[idx];
    float dx = l.x * 0.1f, dy = l.y * 0.1f, dw = l.z * 0.2f, dh = l.w * 0.2f;
    float pcx = cx + dx * ws, pcy = cy + dy * hs;
    float pw = expf(dw) * ws, ph = expf(dh) * hs;
    float bx1 = fminf(fmaxf(pcx - 0.5f * pw, 0.f), 640.f);
    float by1 = fminf(fmaxf(pcy - 0.5f * ph, 0.f), 640.f);
    float bx2 = fminf(fmaxf(pcx + 0.5f * pw, 0.f), 640.f);
    float by2 = fminf(fmaxf(pcy + 0.5f * ph, 0.f), 640.f);
    selBox[r] = make_float4(bx1, by1, bx2, by2);
}

// ---------------- NMS --------------------------------------------------------
__global__ __launch_bounds__(1024)
void iou_mask_k(const float4* __restrict__ boxes, unsigned* __restrict__ mask)
{
    int i = blockIdx.x;
    int j = threadIdx.x;
    float4 bi = boxes[i];
    float4 bj = (j < KTOP) ? boxes[j] : make_float4(0,0,0,0);
    float ai = fmaxf(bi.z - bi.x, 0.f) * fmaxf(bi.w - bi.y, 0.f);
    float aj = fmaxf(bj.z - bj.x, 0.f) * fmaxf(bj.w - bj.y, 0.f);
    float xx1 = fmaxf(bi.x, bj.x), yy1 = fmaxf(bi.y, bj.y);
    float xx2 = fminf(bi.z, bj.z), yy2 = fminf(bi.w, bj.w);
    float inter = fmaxf(xx2 - xx1, 0.f) * fmaxf(yy2 - yy1, 0.f);
    float iou = inter / (ai + aj - inter + 1e-8f);
    bool sup = (j < KTOP) && (j > i) && (iou > 0.5f);
    unsigned bal = __ballot_sync(0xffffffffu, sup);
    if ((j & 31) == 0) mask[i * 32 + (j >> 5)] = bal;
}

__global__ void nms_seq_k(const unsigned* __restrict__ mask,
                          const float* __restrict__ vals,
                          unsigned char* __restrict__ keepOut)
{
    int lane = threadIdx.x;
    unsigned validw = 0;
    #pragma unroll
    for (int b = 0; b < 32; b++) {
        int j = lane * 32 + b;
        if (j < KTOP && vals[j] > 0.f) validw |= (1u << b);
    }
    unsigned remv = 0;
    for (int i = 0; i < KTOP; i++) {
        unsigned row = mask[i * 32 + lane];
        unsigned rm = __shfl_sync(0xffffffffu, remv, i >> 5);
        unsigned vw = __shfl_sync(0xffffffffu, validw, i >> 5);
        unsigned bi = i & 31;
        if (((vw >> bi) & 1) && !((rm >> bi) & 1))
            remv |= row;
    }
    #pragma unroll
    for (int b = 0; b < 32; b++) {
        int j = lane * 32 + b;
        if (j < KTOP)
            keepOut[j] = (unsigned char)(((validw >> b) & 1) && !((remv >> b) & 1));
    }
}

// ---------------- pack output ------------------------------------------------
__global__ void output_k(const float* __restrict__ vals, const int* __restrict__ cls,
                         const float4* __restrict__ boxes,
                         const unsigned char* __restrict__ keep,
                         float* __restrict__ out, int out_size)
{
    int r = blockIdx.x * blockDim.x + threadIdx.x;
    if (r >= KTOP) return;
    bool k = keep[r] != 0;
    float4 b = boxes[r];
    if (r < out_size) out[r] = k ? vals[r] : 0.f;
    if (1000 + r < out_size) out[1000 + r] = (float)cls[r];
    if (2000 + 4 * r + 3 < out_size) {
        out[2000 + 4 * r + 0] = k ? b.x : 0.f;
        out[2000 + 4 * r + 1] = k ? b.y : 0.f;
        out[2000 + 4 * r + 2] = k ? b.z : 0.f;
        out[2000 + 4 * r + 3] = k ? b.w : 0.f;
    }
    if (6000 + r < out_size) out[6000 + r] = k ? 1.f : 0.f;
}

// ---------------- host orchestration -----------------------------------------
extern "C" void kernel_launch(void* const* d_in, const int* in_sizes, int n_in,
                              void* d_out, int out_size)
{
    (void)in_sizes; (void)n_in;
    const float* f0 = (const float*)d_in[0];
    const float* f1 = (const float*)d_in[1];
    const float* f2 = (const float*)d_in[2];
    const float* f3 = (const float*)d_in[3];
    const float* f4 = (const float*)d_in[4];
    const float* cls_w  = (const float*)d_in[5];
    const float* cls_b  = (const float*)d_in[6];
    const float* cls_hw = (const float*)d_in[7];
    const float* cls_hb = (const float*)d_in[8];
    const float* reg_w  = (const float*)d_in[9];
    const float* reg_b  = (const float*)d_in[10];
    const float* reg_hw = (const float*)d_in[11];
    const float* reg_hb = (const float*)d_in[12];

    float *bufA, *bufB, *wTrk, *wCls, *wReg, *clsR, *regR, *scores, *topVal;
    int *arg, *selCls;
    float4 *loc, *selBox;
    ull *keys, *tmpA, *tmpB;
    unsigned *mask;
    unsigned char* keep;
    cudaGetSymbolAddress((void**)&bufA, g_bufA);
    cudaGetSymbolAddress((void**)&bufB, g_bufB);
    cudaGetSymbolAddress((void**)&wTrk, g_wTrunk);
    cudaGetSymbolAddress((void**)&wCls, g_wCls);
    cudaGetSymbolAddress((void**)&wReg, g_wReg);
    cudaGetSymbolAddress((void**)&clsR, g_cls);
    cudaGetSymbolAddress((void**)&regR, g_reg);
    cudaGetSymbolAddress((void**)&scores, g_scores);
    cudaGetSymbolAddress((void**)&arg, g_arg);
    cudaGetSymbolAddress((void**)&loc, g_loc);
    cudaGetSymbolAddress((void**)&keys, g_keys);
    cudaGetSymbolAddress((void**)&tmpA, g_tmpA);
    cudaGetSymbolAddress((void**)&tmpB, g_tmpB);
    cudaGetSymbolAddress((void**)&mask, g_mask);
    cudaGetSymbolAddress((void**)&selBox, g_selBox);
    cudaGetSymbolAddress((void**)&topVal, g_topVal);
    cudaGetSymbolAddress((void**)&selCls, g_selCls);
    cudaGetSymbolAddress((void**)&keep, g_keep);

    static int smemSet = 0;
    if (!smemSet) {
        cudaFuncSetAttribute(conv_trunk_k, cudaFuncAttributeMaxDynamicSharedMemorySize, DYN_SMEM);
        cudaFuncSetAttribute(conv_head_k,  cudaFuncAttributeMaxDynamicSharedMemorySize, DYN_SMEM);
        smemSet = 1;
    }

    const int TOTW = 2*TRKN + 256*9*768 + 256*9*128;
    transpose_all_k<<<CDIV(TOTW,256), 256>>>(cls_w, reg_w, cls_hw, reg_hw, wTrk, wCls, wReg);

    dim3 gt(139, 2, 2);
    conv_trunk_k<<<gt, 256, DYN_SMEM>>>(f0,f1,f2,f3,f4, nullptr, bufA, wTrk, cls_b, reg_b, 0, 1);
    conv_trunk_k<<<gt, 256, DYN_SMEM>>>(f0,f1,f2,f3,f4, bufA,    bufB, wTrk, cls_b, reg_b, 1, 0);
    conv_trunk_k<<<gt, 256, DYN_SMEM>>>(f0,f1,f2,f3,f4, bufB,    bufA, wTrk, cls_b, reg_b, 2, 0);
    conv_trunk_k<<<gt, 256, DYN_SMEM>>>(f0,f1,f2,f3,f4, bufA,    bufB, wTrk, cls_b, reg_b, 3, 0);
    dim3 gh(139, 7, 1);
    conv_head_k<<<gh, 256, DYN_SMEM>>>(bufB, clsR, regR, wCls, wReg, cls_hb, reg_hb);

    score_key_sort_k<<<N_SORT / 2048, 1024>>>(clsR, regR, scores, arg, loc, keys);

    topk_merge_k<<<32, 512>>>(keys, tmpA, 2048);
    topk_merge_k<<<16, 512>>>(tmpA, tmpB, 1024);
    topk_merge_k<<< 8, 512>>>(tmpB, tmpA, 1024);
    topk_merge_k<<< 4, 512>>>(tmpA, tmpB, 1024);
    topk_merge_k<<< 2, 512>>>(tmpB, tmpA, 1024);
    topk_merge_k<<< 1, 512>>>(tmpA, tmpB, 1024);

    decode_k<<<CDIV(KTOP, 256), 256>>>(tmpB, scores, arg, loc, selBox, topVal, selCls);
    iou_mask_k<<<KTOP, 1024>>>(selBox, mask);
    nms_seq_k<<<1, 32>>>(mask, topVal, keep);
    output_k<<<CDIV(KTOP, 256), 256>>>(topVal, selCls, selBox, keep,
                                       (float*)d_out, out_size);
}

// round 13
// speedup vs baseline: 1.7754x; 1.0786x over previous
#include <cuda_runtime.h>
#include <math.h>

#define CDIV(a,b) (((a)+(b)-1)/(b))
#define N_ANCH 76725
#define N_SORT 131072
#define KTOP   1000
#define TS     (256*8525)
typedef unsigned long long ull;

// dynamic smem layout: wBuf[2][9216] floats, then inBuf[2][1120] floats
#define WBUF_FLOATS 9216
#define INBUF_FLOATS 1120
#define DYN_SMEM (2*WBUF_FLOATS*4 + 2*INBUF_FLOATS*4)   // 82688 B

// ---------------- scratch (static device globals; no allocation) -------------
__device__ float g_bufA[2*TS];
__device__ float g_bufB[2*TS];
__device__ float g_wTrunk[2*4*256*9*256];      // [tower][layer][ci][k][co]
__device__ float g_wCls[256*9*768];
__device__ float g_wReg[256*9*64];             // reg head padded 36 -> 64
__device__ float g_cls[720*8525];
__device__ float g_reg[36*8525];
__device__ float g_scores[N_ANCH];
__device__ int   g_arg[N_ANCH];
__device__ float4 g_loc[N_ANCH];
__device__ ull   g_keys[N_SORT];
__device__ ull   g_tmpA[32*1024];
__device__ ull   g_tmpB[16*1024];
__device__ unsigned g_mask[KTOP*32];
__device__ float4 g_selBox[KTOP];
__device__ float  g_topVal[KTOP];
__device__ int    g_selCls[KTOP];
__device__ unsigned char g_keep[KTOP];

// ---------------- fused weight transpose -------------------------------------
#define TRKN (4*256*9*256)
__global__ void transpose_all_k(const float* __restrict__ cls_w,
                                const float* __restrict__ reg_w,
                                const float* __restrict__ cls_hw,
                                const float* __restrict__ reg_hw,
                                float* __restrict__ wTrk,
                                float* __restrict__ wCls,
                                float* __restrict__ wReg)
{
    int idx = blockIdx.x * blockDim.x + threadIdx.x;
    if (idx < 2*TRKN) {
        const float* src = (idx < TRKN) ? cls_w : reg_w;
        int i = (idx < TRKN) ? idx : idx - TRKN;
        int co = i & 255, r = i >> 8;
        int kk = r % 9, r2 = r / 9;
        int ci = r2 & 255, layer = r2 >> 8;
        wTrk[idx] = src[((layer*256 + co)*256 + ci)*9 + kk];
        return;
    }
    idx -= 2*TRKN;
    if (idx < 256*9*768) {
        int co = idx % 768, r = idx / 768;
        int kk = r % 9, ci = r / 9;
        wCls[idx] = (co < 720) ? cls_hw[(co*256 + ci)*9 + kk] : 0.f;
        return;
    }
    idx -= 256*9*768;
    if (idx < 256*9*64) {
        int co = idx % 64, r = idx / 64;
        int kk = r % 9, ci = r / 9;
        wReg[idx] = (co < 36) ? reg_hw[(co*256 + ci)*9 + kk] : 0.f;
    }
}

// ---------------- helpers ----------------------------------------------------
__device__ __forceinline__ void ffma2(ull& d, ull a, ull b) {
    asm("fma.rn.f32x2 %0, %1, %2, %0;" : "+l"(d) : "l"(a), "l"(b));
}
__device__ __forceinline__ ull pack2(float v) {
    ull r; asm("mov.b64 %0, {%1, %1};" : "=l"(r) : "f"(v)); return r;
}
__device__ __forceinline__ float lo32(ull a) { return __uint_as_float((unsigned)a); }
__device__ __forceinline__ float hi32(ull a) { return __uint_as_float((unsigned)(a >> 32)); }
__device__ __forceinline__ void cp_async16(unsigned saddr, const void* gptr) {
    asm volatile("cp.async.cg.shared.global [%0], [%1], 16;" :: "r"(saddr), "l"(gptr));
}
#define CP_COMMIT() asm volatile("cp.async.commit_group;")
#define CP_WAIT0()  asm volatile("cp.async.wait_group 0;")

__device__ __forceinline__ void tile_decode(int t, int& L, int& H, int& hwBase,
                                            int& x0, int& y0)
{
    int tpr;
    if      (t < 100) { L=0; H=80; hwBase=0;    tpr=10; }
    else if (t < 125) { L=1; H=40; hwBase=6400; tpr=5;  t-=100; }
    else if (t < 134) { L=2; H=20; hwBase=8000; tpr=3;  t-=125; }
    else if (t < 138) { L=3; H=10; hwBase=8400; tpr=2;  t-=134; }
    else              { L=4; H=5;  hwBase=8500; tpr=1;  t-=138; }
    x0 = (t % tpr) * 8; y0 = (t / tpr) * 8;
}

// ---------------- conv core (templated co-block width) ------------------------
template<int COB>
__device__ __forceinline__ void conv_core(
    const float* __restrict__ in, const float* __restrict__ wT, int STR,
    int coBase, const float* __restrict__ bias, float* __restrict__ out,
    int Cout, int relu, int H, int x0, int y0)
{
    extern __shared__ __align__(16) char dynsmem[];
    float* wBuf = (float*)dynsmem;                              // [2][9216]
    float* inBuf = (float*)(dynsmem + 2*WBUF_FLOATS*4);         // [2][1120]

    constexpr int NPR = COB / 32;          // ull pairs per thread (4 or 2)
    constexpr int WCHUNKS = 72 * COB / 4;  // 16B chunks per weight stage
    constexpr int WPT = (WCHUNKS + 255) / 256;
    constexpr int LPR = COB / 4;           // 16B lanes per row

    const int W = H, HW = H * W;
    const int tid = threadIdx.x;
    const int p = tid & 15, q = tid >> 4;
    const int pyb = (p >> 2) * 2, pxb = (p & 3) * 2;
    const int coQ = q * (COB / 16);

    int  sAddr[4]; int gInv[4]; bool okL[4], okS[4];
    #pragma unroll
    for (int j = 0; j < 4; j++) {
        int idx = tid + j * 256;
        int ci = idx / 100, r = idx % 100, dy = r / 10, dx = r % 10;
        int gy = y0 - 1 + dy, gx = x0 - 1 + dx;
        okS[j] = idx < 800;
        okL[j] = okS[j] && gy >= 0 && gy < H && gx >= 0 && gx < W;
        gInv[j] = okL[j] ? (ci * HW + gy * W + gx) : 0;
        sAddr[j] = ci * 140 + dy * 14 + dx;
    }

    auto issueW = [&](int chunk, int bIdx) {
        const float* wp = wT + chunk * 72 * STR + coBase;
        unsigned sb = (unsigned)__cvta_generic_to_shared(wBuf + bIdx * WBUF_FLOATS);
        #pragma unroll
        for (int c = 0; c < WPT; c++) {
            int i = tid + c * 256;
            if (WCHUNKS % 256 == 0 || i < WCHUNKS) {
                int row = i / LPR, lane = i % LPR;
                cp_async16(sb + row * (COB*4) + lane * 16, wp + row * STR + lane * 4);
            }
        }
        CP_COMMIT();
    };
    auto loadIn = [&](int chunk, float vreg[4]) {
        #pragma unroll
        for (int j = 0; j < 4; j++)
            vreg[j] = okL[j] ? __ldg(in + gInv[j] + chunk * 8 * HW) : 0.f;
    };
    auto storeIn = [&](int bIdx, const float vreg[4]) {
        #pragma unroll
        for (int j = 0; j < 4; j++)
            if (okS[j]) inBuf[bIdx * INBUF_FLOATS + sAddr[j]] = vreg[j];
    };

    {
        float v0[4];
        issueW(0, 0);
        loadIn(0, v0);
        storeIn(0, v0);
        CP_WAIT0();
    }
    __syncthreads();

    ull acc[2][2][NPR] = {};

    #pragma unroll 1
    for (int chunk = 0; chunk < 32; chunk++) {
        const int cur = chunk & 1;
        const bool more = (chunk + 1) < 32;
        float vnext[4];
        if (more) { issueW(chunk + 1, cur ^ 1); loadIn(chunk + 1, vnext); }

        const float* s_w = wBuf + cur * WBUF_FLOATS;
        const float* s_base = inBuf + cur * INBUF_FLOATS;

        #pragma unroll 1
        for (int ci = 0; ci < 8; ci++) {
            const float* rowb = s_base + ci * 140;
            const float* wcb = s_w + ci * 9 * COB + coQ;
            ull iv[4][4];
            #pragma unroll
            for (int r = 0; r < 4; r++) {
                const float2* rp = (const float2*)(rowb + (pyb + r) * 14 + pxb);
                float2 v0 = rp[0], v1 = rp[1];
                iv[r][0] = pack2(v0.x); iv[r][1] = pack2(v0.y);
                iv[r][2] = pack2(v1.x); iv[r][3] = pack2(v1.y);
            }
            #pragma unroll
            for (int ky = 0; ky < 3; ky++) {
                #pragma unroll
                for (int kx = 0; kx < 3; kx++) {
                    const float* wrow = wcb + (ky * 3 + kx) * COB;
                    ull wv[NPR];
                    #pragma unroll
                    for (int pr = 0; pr < NPR; pr++)
                        wv[pr] = *(const ull*)(wrow + pr * 2);
                    #pragma unroll
                    for (int py = 0; py < 2; py++)
                        #pragma unroll
                        for (int px = 0; px < 2; px++) {
                            ull v = iv[ky + py][px + kx];
                            #pragma unroll
                            for (int pr = 0; pr < NPR; pr++)
                                ffma2(acc[py][px][pr], v, wv[pr]);
                        }
                }
            }
        }

        if (more) { storeIn(cur ^ 1, vnext); CP_WAIT0(); }
        __syncthreads();
    }

    #pragma unroll
    for (int pr = 0; pr < NPR; pr++) {
        int c0 = coBase + coQ + pr * 2, c1 = c0 + 1;
        if (c0 >= Cout) continue;
        float b0 = bias[c0];
        float b1 = (c1 < Cout) ? bias[c1] : 0.f;
        #pragma unroll
        for (int py = 0; py < 2; py++) {
            int y = y0 + pyb + py;
            if (y >= H) continue;
            #pragma unroll
            for (int px = 0; px < 2; px++) {
                int x = x0 + pxb + px;
                if (x >= W) continue;
                float v0 = lo32(acc[py][px][pr]) + b0;
                float v1 = hi32(acc[py][px][pr]) + b1;
                if (relu) { v0 = fmaxf(v0, 0.f); v1 = fmaxf(v1, 0.f); }
                out[c0 * HW + y * W + x] = v0;
                if (c1 < Cout) out[c1 * HW + y * W + x] = v1;
            }
        }
    }
}

__global__ __launch_bounds__(256, 2)
void conv_trunk_k(const float* f0, const float* f1, const float* f2,
                  const float* f3, const float* f4,
                  const float* __restrict__ actIn, float* __restrict__ actOut,
                  const float* __restrict__ wT,
                  const float* __restrict__ biasCls, const float* __restrict__ biasReg,
                  int layer, int isFirst)
{
    int L, H, hwBase, x0, y0;
    tile_decode(blockIdx.x, L, H, hwBase, x0, y0);
    const int tower = blockIdx.z;
    const int coBase = blockIdx.y * 128;
    const float* in;
    if (isFirst) {
        const float* fs[5] = {f0, f1, f2, f3, f4};
        in = fs[L];
    } else {
        in = actIn + tower * TS + hwBase * 256;
    }
    const float* w = wT + (tower * 4 + layer) * (256*9*256);
    const float* b = (tower ? biasReg : biasCls) + layer * 256;
    float* out = actOut + tower * TS + hwBase * 256;
    conv_core<128>(in, w, 256, coBase, b, out, 256, 1, H, x0, y0);
}

__global__ __launch_bounds__(256, 2)
void conv_head_k(const float* __restrict__ actIn,
                 float* __restrict__ outCls, float* __restrict__ outReg,
                 const float* __restrict__ wTc, const float* __restrict__ wTr,
                 const float* __restrict__ biasC, const float* __restrict__ biasR)
{
    int L, H, hwBase, x0, y0;
    tile_decode(blockIdx.x, L, H, hwBase, x0, y0);
    const int yy = blockIdx.y;
    if (yy < 6) {
        const float* in = actIn + 0 * TS + hwBase * 256;
        conv_core<128>(in, wTc, 768, yy * 128, biasC, outCls + 720 * hwBase, 720, 0, H, x0, y0);
    } else {
        const float* in = actIn + 1 * TS + hwBase * 256;
        conv_core<64>(in, wTr, 64, 0, biasR, outReg + 36 * hwBase, 36, 0, H, x0, y0);
    }
}

// ---------------- fused scores/argmax/keys + block-local sort ----------------
// Lazy sigmoid argmax: float sigmoid is weakly monotone in the logit, so
// max-sigmoid = sigmoid(max-logit). If that saturates to 1.0f (true for ~all
// anchors here), reference argmax = FIRST class whose sigmoid rounds to 1.0f;
// sigmoid(x) < 1.0f for x < 16, so only candidates >= 16 need expf.
__global__ __launch_bounds__(1024)
void score_key_sort_k(const float* __restrict__ cls_raw,
                      const float* __restrict__ reg_raw,
                      float* __restrict__ scores, int* __restrict__ arg,
                      float4* __restrict__ loc,
                      ull* __restrict__ keys)
{
    __shared__ ull s[2048];
    int tid = threadIdx.x;

    #pragma unroll
    for (int h = 0; h < 2; h++) {
        int t = blockIdx.x * 2048 + tid + h * 1024;
        ull key = 0xFFFFFFFFFFFFFFFFULL;
        if (t < N_ANCH) {
            int L, a, p, HW, cum;
            if      (t < 57600) { L=0; int rel=t;       HW=6400; a=rel/6400; p=rel%6400; cum=0;    }
            else if (t < 72000) { L=1; int rel=t-57600; HW=1600; a=rel/1600; p=rel%1600; cum=6400; }
            else if (t < 75600) { L=2; int rel=t-72000; HW=400;  a=rel/400;  p=rel%400;  cum=8000; }
            else if (t < 76500) { L=3; int rel=t-75600; HW=100;  a=rel/100;  p=rel%100;  cum=8400; }
            else                { L=4; int rel=t-76500; HW=25;   a=rel/25;   p=rel%25;   cum=8500; }
            const int aoff[5] = {0, 57600, 72000, 75600, 76500};
            int idx = aoff[L] + p * 9 + a;

            const float* cb = cls_raw + 720 * cum + (a * 80) * HW + p;

            // pass 1: max logit (no expf)
            float mx = cb[0];
            for (int c = 1; c < 80; c++) {
                float v = cb[c * HW];
                if (v > mx) mx = v;
            }
            float S = 1.f / (1.f + expf(-mx));
            int barg;
            if (S == 1.0f) {
                barg = 0;
                for (int c = 0; c < 80; c++) {
                    float v = cb[c * HW];
                    if (v >= 16.0f) {
                        float sg = 1.f / (1.f + expf(-v));
                        if (sg == 1.0f) { barg = c; break; }
                    }
                }
            } else {
                // exact fallback: replicate original full scan
                float best = 1.f / (1.f + expf(-cb[0]));
                barg = 0;
                for (int c = 1; c < 80; c++) {
                    float sg = 1.f / (1.f + expf(-cb[c * HW]));
                    if (sg > best) { best = sg; barg = c; }
                }
                S = best;
            }
            float masked = (S > 0.05f) ? S : -1.0f;
            scores[idx] = masked;
            arg[idx] = barg;

            const float* rb = reg_raw + 36 * cum + (a * 4) * HW + p;
            loc[idx] = make_float4(rb[0], rb[HW], rb[2 * HW], rb[3 * HW]);

            unsigned u = __float_as_uint(masked);
            u = (u & 0x80000000u) ? ~u : (u | 0x80000000u);
            key = (((ull)(~u)) << 32) | (unsigned)idx;
        }
        s[tid + h * 1024] = key;
    }
    __syncthreads();

    for (int k = 2; k <= 2048; k <<= 1) {
        for (int j = k >> 1; j >= 1; j >>= 1) {
            #pragma unroll
            for (int h = 0; h < 2; h++) {
                int l = tid + h * 1024;
                int ixj = l ^ j;
                if (ixj > l) {
                    ull a = s[l], b = s[ixj];
                    bool up = ((l & k) == 0);
                    if ((a > b) == up) { s[l] = b; s[ixj] = a; }
                }
            }
            __syncthreads();
        }
    }
    keys[blockIdx.x * 2048 + tid] = s[tid];
    keys[blockIdx.x * 2048 + tid + 1024] = s[tid + 1024];
}

// ---------------- tournament merge: 2 sorted-1024 lists -> best 1024 ---------
__global__ __launch_bounds__(512)
void topk_merge_k(const ull* __restrict__ in, ull* __restrict__ out, int inStride)
{
    __shared__ ull s[2048];
    int t = threadIdx.x;
    const ull* A = in + (size_t)blockIdx.x * 2 * inStride;
    const ull* B = A + inStride;
    #pragma unroll
    for (int i = t; i < 1024; i += 512) {
        s[i] = A[i];
        s[2047 - i] = B[i];
    }
    __syncthreads();
    for (int j = 1024; j >= 1; j >>= 1) {
        #pragma unroll
        for (int h = 0; h < 4; h++) {
            int l = t + h * 512;
            int ixj = l ^ j;
            if (ixj > l) {
                ull a = s[l], b = s[ixj];
                if (a > b) { s[l] = b; s[ixj] = a; }
            }
        }
        __syncthreads();
    }
    #pragma unroll
    for (int i = t; i < 1024; i += 512)
        out[blockIdx.x * 1024 + i] = s[i];
}

// ---------------- decode top-1000 boxes --------------------------------------
__device__ __forceinline__ void anchor_split(int idx, int& L, int& p, int& a, int& Wd)
{
    const int aoff[6] = {0, 57600, 72000, 75600, 76500, 76725};
    const int Ws[5] = {80, 40, 20, 10, 5};
    L = 0;
    while (L < 4 && idx >= aoff[L + 1]) L++;
    int rel = idx - aoff[L];
    p = rel / 9; a = rel - p * 9; Wd = Ws[L];
}

__global__ void decode_k(const ull* __restrict__ keys,
                         const float* __restrict__ scores,
                         const int* __restrict__ arg,
                         const float4* __restrict__ loc,
                         float4* __restrict__ selBox, float* __restrict__ topVal,
                         int* __restrict__ selCls)
{
    int r = blockIdx.x * blockDim.x + threadIdx.x;
    if (r >= KTOP) return;
    int idx = (int)(keys[r] & 0xFFFFFFFFULL);
    float val = scores[idx];
    topVal[r] = val;
    selCls[r] = arg[idx];

    const int strides[5] = {8, 16, 32, 64, 128};
    const int sizes[5] = {32, 64, 128, 256, 512};
    int L, p, a, W;
    anchor_split(idx, L, p, a, W);
    int y = p / W, x = p - y * W;
    int ri = a / 3, si = a - ri * 3;
    const float ratios[3] = {0.5f, 1.0f, 2.0f};
    const float scales[3] = {1.0f, 1.2599210498948732f, 1.5874010519681994f};
    float sq = sqrtf(ratios[ri]);
    float ws = (float)sizes[L] * scales[si] / sq;
    float hs = (float)sizes[L] * scales[si] * sq;
    float st = (float)strides[L];
    float cx = ((float)x + 0.5f) * st;
    float cy = ((float)y + 0.5f) * st;

    float4 l = loc[idx];
    float dx = l.x * 0.1f, dy = l.y * 0.1f, dw = l.z * 0.2f, dh = l.w * 0.2f;
    float pcx = cx + dx * ws, pcy = cy + dy * hs;
    float pw = expf(dw) * ws, ph = expf(dh) * hs;
    float bx1 = fminf(fmaxf(pcx - 0.5f * pw, 0.f), 640.f);
    float by1 = fminf(fmaxf(pcy - 0.5f * ph, 0.f), 640.f);
    float bx2 = fminf(fmaxf(pcx + 0.5f * pw, 0.f), 640.f);
    float by2 = fminf(fmaxf(pcy + 0.5f * ph, 0.f), 640.f);
    selBox[r] = make_float4(bx1, by1, bx2, by2);
}

// ---------------- NMS --------------------------------------------------------
__global__ __launch_bounds__(1024)
void iou_mask_k(const float4* __restrict__ boxes, unsigned* __restrict__ mask)
{
    int i = blockIdx.x;
    int j = threadIdx.x;
    float4 bi = boxes[i];
    float4 bj = (j < KTOP) ? boxes[j] : make_float4(0,0,0,0);
    float ai = fmaxf(bi.z - bi.x, 0.f) * fmaxf(bi.w - bi.y, 0.f);
    float aj = fmaxf(bj.z - bj.x, 0.f) * fmaxf(bj.w - bj.y, 0.f);
    float xx1 = fmaxf(bi.x, bj.x), yy1 = fmaxf(bi.y, bj.y);
    float xx2 = fminf(bi.z, bj.z), yy2 = fminf(bi.w, bj.w);
    float inter = fmaxf(xx2 - xx1, 0.f) * fmaxf(yy2 - yy1, 0.f);
    float iou = inter / (ai + aj - inter + 1e-8f);
    bool sup = (j < KTOP) && (j > i) && (iou > 0.5f);
    unsigned bal = __ballot_sync(0xffffffffu, sup);
    if ((j & 31) == 0) mask[i * 32 + (j >> 5)] = bal;
}

__global__ void nms_seq_k(const unsigned* __restrict__ mask,
                          const float* __restrict__ vals,
                          unsigned char* __restrict__ keepOut)
{
    int lane = threadIdx.x;
    unsigned validw = 0;
    #pragma unroll
    for (int b = 0; b < 32; b++) {
        int j = lane * 32 + b;
        if (j < KTOP && vals[j] > 0.f) validw |= (1u << b);
    }
    unsigned remv = 0;
    for (int i = 0; i < KTOP; i++) {
        unsigned row = mask[i * 32 + lane];
        unsigned rm = __shfl_sync(0xffffffffu, remv, i >> 5);
        unsigned vw = __shfl_sync(0xffffffffu, validw, i >> 5);
        unsigned bi = i & 31;
        if (((vw >> bi) & 1) && !((rm >> bi) & 1))
            remv |= row;
    }
    #pragma unroll
    for (int b = 0; b < 32; b++) {
        int j = lane * 32 + b;
        if (j < KTOP)
            keepOut[j] = (unsigned char)(((validw >> b) & 1) && !((remv >> b) & 1));
    }
}

// ---------------- pack output ------------------------------------------------
__global__ void output_k(const float* __restrict__ vals, const int* __restrict__ cls,
                         const float4* __restrict__ boxes,
                         const unsigned char* __restrict__ keep,
                         float* __restrict__ out, int out_size)
{
    int r = blockIdx.x * blockDim.x + threadIdx.x;
    if (r >= KTOP) return;
    bool k = keep[r] != 0;
    float4 b = boxes[r];
    if (r < out_size) out[r] = k ? vals[r] : 0.f;
    if (1000 + r < out_size) out[1000 + r] = (float)cls[r];
    if (2000 + 4 * r + 3 < out_size) {
        out[2000 + 4 * r + 0] = k ? b.x : 0.f;
        out[2000 + 4 * r + 1] = k ? b.y : 0.f;
        out[2000 + 4 * r + 2] = k ? b.z : 0.f;
        out[2000 + 4 * r + 3] = k ? b.w : 0.f;
    }
    if (6000 + r < out_size) out[6000 + r] = k ? 1.f : 0.f;
}

// ---------------- host orchestration -----------------------------------------
extern "C" void kernel_launch(void* const* d_in, const int* in_sizes, int n_in,
                              void* d_out, int out_size)
{
    (void)in_sizes; (void)n_in;
    const float* f0 = (const float*)d_in[0];
    const float* f1 = (const float*)d_in[1];
    const float* f2 = (const float*)d_in[2];
    const float* f3 = (const float*)d_in[3];
    const float* f4 = (const float*)d_in[4];
    const float* cls_w  = (const float*)d_in[5];
    const float* cls_b  = (const float*)d_in[6];
    const float* cls_hw = (const float*)d_in[7];
    const float* cls_hb = (const float*)d_in[8];
    const float* reg_w  = (const float*)d_in[9];
    const float* reg_b  = (const float*)d_in[10];
    const float* reg_hw = (const float*)d_in[11];
    const float* reg_hb = (const float*)d_in[12];

    float *bufA, *bufB, *wTrk, *wCls, *wReg, *clsR, *regR, *scores, *topVal;
    int *arg, *selCls;
    float4 *loc, *selBox;
    ull *keys, *tmpA, *tmpB;
    unsigned *mask;
    unsigned char* keep;
    cudaGetSymbolAddress((void**)&bufA, g_bufA);
    cudaGetSymbolAddress((void**)&bufB, g_bufB);
    cudaGetSymbolAddress((void**)&wTrk, g_wTrunk);
    cudaGetSymbolAddress((void**)&wCls, g_wCls);
    cudaGetSymbolAddress((void**)&wReg, g_wReg);
    cudaGetSymbolAddress((void**)&clsR, g_cls);
    cudaGetSymbolAddress((void**)&regR, g_reg);
    cudaGetSymbolAddress((void**)&scores, g_scores);
    cudaGetSymbolAddress((void**)&arg, g_arg);
    cudaGetSymbolAddress((void**)&loc, g_loc);
    cudaGetSymbolAddress((void**)&keys, g_keys);
    cudaGetSymbolAddress((void**)&tmpA, g_tmpA);
    cudaGetSymbolAddress((void**)&tmpB, g_tmpB);
    cudaGetSymbolAddress((void**)&mask, g_mask);
    cudaGetSymbolAddress((void**)&selBox, g_selBox);
    cudaGetSymbolAddress((void**)&topVal, g_topVal);
    cudaGetSymbolAddress((void**)&selCls, g_selCls);
    cudaGetSymbolAddress((void**)&keep, g_keep);

    static int smemSet = 0;
    if (!smemSet) {
        cudaFuncSetAttribute(conv_trunk_k, cudaFuncAttributeMaxDynamicSharedMemorySize, DYN_SMEM);
        cudaFuncSetAttribute(conv_head_k,  cudaFuncAttributeMaxDynamicSharedMemorySize, DYN_SMEM);
        smemSet = 1;
    }

    const int TOTW = 2*TRKN + 256*9*768 + 256*9*64;
    transpose_all_k<<<CDIV(TOTW,256), 256>>>(cls_w, reg_w, cls_hw, reg_hw, wTrk, wCls, wReg);

    dim3 gt(139, 2, 2);
    conv_trunk_k<<<gt, 256, DYN_SMEM>>>(f0,f1,f2,f3,f4, nullptr, bufA, wTrk, cls_b, reg_b, 0, 1);
    conv_trunk_k<<<gt, 256, DYN_SMEM>>>(f0,f1,f2,f3,f4, bufA,    bufB, wTrk, cls_b, reg_b, 1, 0);
    conv_trunk_k<<<gt, 256, DYN_SMEM>>>(f0,f1,f2,f3,f4, bufB,    bufA, wTrk, cls_b, reg_b, 2, 0);
    conv_trunk_k<<<gt, 256, DYN_SMEM>>>(f0,f1,f2,f3,f4, bufA,    bufB, wTrk, cls_b, reg_b, 3, 0);
    dim3 gh(139, 7, 1);
    conv_head_k<<<gh, 256, DYN_SMEM>>>(bufB, clsR, regR, wCls, wReg, cls_hb, reg_hb);

    score_key_sort_k<<<N_SORT / 2048, 1024>>>(clsR, regR, scores, arg, loc, keys);

    topk_merge_k<<<32, 512>>>(keys, tmpA, 2048);
    topk_merge_k<<<16, 512>>>(tmpA, tmpB, 1024);
    topk_merge_k<<< 8, 512>>>(tmpB, tmpA, 1024);
    topk_merge_k<<< 4, 512>>>(tmpA, tmpB, 1024);
    topk_merge_k<<< 2, 512>>>(tmpB, tmpA, 1024);
    topk_merge_k<<< 1, 512>>>(tmpA, tmpB, 1024);

    decode_k<<<CDIV(KTOP, 256), 256>>>(tmpB, scores, arg, loc, selBox, topVal, selCls);
    iou_mask_k<<<KTOP, 1024>>>(selBox, mask);
    nms_seq_k<<<1, 32>>>(mask, topVal, keep);
    output_k<<<CDIV(KTOP, 256), 256>>>(topVal, selCls, selBox, keep,
                                       (float*)d_out, out_size);
}